// round 11
// baseline (speedup 1.0000x reference)
#include <cuda_runtime.h>
#include <cuda_fp16.h>
#include <cuda_bf16.h>
#include <math.h>

#define NPOS 4096
#define FULLM 0xffffffffu

// ---------------- scratch (static device globals; no allocation) -------------
__device__ float g_qkv[NPOS * 576];            // (pos, 576) pos-major fp32
__device__ float g_x2 [192 * NPOS];            // (C, pos) fp32
__device__ float g_sums[2 * 192];              // per-channel sum / sumsq
__device__ float g_mult[192];                  // scale*gamma/rms
// bf16 big/small pairs
__device__ __nv_bfloat16 g_wb [768 * 192],  g_wsm[768 * 192];    // W bank 0 (qkv, then mlp_w1)
__device__ __nv_bfloat16 g_wb2[192 * 768],  g_ws2[192 * 768];    // W bank 1 (proj, then mlp_w2)
__device__ __nv_bfloat16 g_xb [192 * NPOS], g_xs [192 * NPOS];   // x pairs (C,N)
__device__ __nv_bfloat16 g_obb[NPOS * 192], g_obs[NPOS * 192];   // attn out pairs (N,C)
__device__ __nv_bfloat16 g_x2b[192 * NPOS], g_x2s[192 * NPOS];   // x2 pairs (C,N)
__device__ __nv_bfloat16 g_mbb[768 * NPOS], g_mbs[768 * NPOS];   // mlp hidden pairs (C,N)

// ---------------- helpers -----------------------------------------------------
__device__ __forceinline__ unsigned smem_u32(const void* p) {
    return (unsigned)__cvta_generic_to_shared(p);
}
__device__ __forceinline__ void cp16(unsigned dst, const void* src) {
    asm volatile("cp.async.cg.shared.global [%0], [%1], 16;" :: "r"(dst), "l"(src));
}
__device__ __forceinline__ void cp_commit() { asm volatile("cp.async.commit_group;"); }
template <int W> __device__ __forceinline__ void cp_wait() {
    asm volatile("cp.async.wait_group %0;" :: "n"(W));
}
__device__ __forceinline__ void mma_bf16(float* d, const unsigned* a, const unsigned* b) {
    asm volatile(
        "mma.sync.aligned.m16n8k16.row.col.f32.bf16.bf16.f32 "
        "{%0,%1,%2,%3},{%4,%5,%6,%7},{%8,%9},{%0,%1,%2,%3};"
        : "+f"(d[0]), "+f"(d[1]), "+f"(d[2]), "+f"(d[3])
        : "r"(a[0]), "r"(a[1]), "r"(a[2]), "r"(a[3]), "r"(b[0]), "r"(b[1]));
}
__device__ __forceinline__ void ldsm_x2_trans(unsigned& r0, unsigned& r1, unsigned addr) {
    asm volatile("ldmatrix.sync.aligned.m8n8.x2.trans.shared.b16 {%0,%1}, [%2];"
                 : "=r"(r0), "=r"(r1) : "r"(addr));
}
__device__ __forceinline__ void store_pair(__nv_bfloat16* pb, __nv_bfloat16* ps,
                                           size_t idx, float v0, float v1) {
    __nv_bfloat16 b0 = __float2bfloat16_rn(v0), b1 = __float2bfloat16_rn(v1);
    __nv_bfloat16 s0 = __float2bfloat16_rn(v0 - __bfloat162float(b0));
    __nv_bfloat16 s1 = __float2bfloat16_rn(v1 - __bfloat162float(b1));
    *(__nv_bfloat162*)(pb + idx) = __halves2bfloat162(b0, b1);
    *(__nv_bfloat162*)(ps + idx) = __halves2bfloat162(s0, s1);
}
__device__ __forceinline__ void split4(float4 v, __nv_bfloat16* db, __nv_bfloat16* ds, int idx) {
    __nv_bfloat16 b0 = __float2bfloat16_rn(v.x), b1 = __float2bfloat16_rn(v.y);
    __nv_bfloat16 b2 = __float2bfloat16_rn(v.z), b3 = __float2bfloat16_rn(v.w);
    *(__nv_bfloat162*)(db + idx)     = __halves2bfloat162(b0, b1);
    *(__nv_bfloat162*)(db + idx + 2) = __halves2bfloat162(b2, b3);
    *(__nv_bfloat162*)(ds + idx) = __halves2bfloat162(
        __float2bfloat16_rn(v.x - __bfloat162float(b0)),
        __float2bfloat16_rn(v.y - __bfloat162float(b1)));
    *(__nv_bfloat162*)(ds + idx + 2) = __halves2bfloat162(
        __float2bfloat16_rn(v.z - __bfloat162float(b2)),
        __float2bfloat16_rn(v.w - __bfloat162float(b3)));
}

// ---------------- per-channel stats over x + bf16 pair conversion -------------
__global__ void colstats_kernel(const float* __restrict__ x,
                                __nv_bfloat16* __restrict__ xb,
                                __nv_bfloat16* __restrict__ xs) {
    int c = blockIdx.x;
    const float* p = x + c * NPOS;
    float s = 0.f, s2 = 0.f;
    for (int i = threadIdx.x; i < NPOS; i += 256) {
        float v = p[i];
        s += v;
        s2 = fmaf(v, v, s2);
        __nv_bfloat16 b = __float2bfloat16_rn(v);
        xb[c * NPOS + i] = b;
        xs[c * NPOS + i] = __float2bfloat16_rn(v - __bfloat162float(b));
    }
    __shared__ float sh0[256], sh1[256];
    sh0[threadIdx.x] = s; sh1[threadIdx.x] = s2;
    __syncthreads();
    for (int o = 128; o > 0; o >>= 1) {
        if (threadIdx.x < o) {
            sh0[threadIdx.x] += sh0[threadIdx.x + o];
            sh1[threadIdx.x] += sh1[threadIdx.x + o];
        }
        __syncthreads();
    }
    if (threadIdx.x == 0) {
        g_sums[c]       = sh0[0];
        g_sums[192 + c] = sh1[0];
    }
}

// ---------------- merged norm-MLP -> g_mult (12 blocks x 256 thr) -------------
// Each block redundantly computes full h[384] (coalesced warp-dots; w1 hits L2),
// then its 16 g_mult outputs. Does NOT zero g_sums (attn does, later in stream).
__global__ void gamma_kernel(const float* __restrict__ w1, const float* __restrict__ b1,
                             const float* __restrict__ w2, const float* __restrict__ b2,
                             const float* __restrict__ scale) {
    __shared__ float stats[192];
    __shared__ float h[384];
    const int t = threadIdx.x, warp = t >> 5, lane = t & 31;
    if (t < 192) stats[t] = g_sums[t] * (1.0f / 4096.0f);
    __syncthreads();

    // layer 1: 8 warps x 4 outputs x 12 sweeps = 384
    #pragma unroll
    for (int g = 0; g < 12; g++) {
        int ob = g * 32 + warp * 4;
        float a0 = 0.f, a1 = 0.f, a2 = 0.f, a3 = 0.f;
        #pragma unroll
        for (int j = 0; j < 6; j++) {
            float sv = stats[lane + j * 32];
            a0 = fmaf(sv, w1[(ob + 0) * 192 + lane + j * 32], a0);
            a1 = fmaf(sv, w1[(ob + 1) * 192 + lane + j * 32], a1);
            a2 = fmaf(sv, w1[(ob + 2) * 192 + lane + j * 32], a2);
            a3 = fmaf(sv, w1[(ob + 3) * 192 + lane + j * 32], a3);
        }
        #pragma unroll
        for (int off = 16; off; off >>= 1) {
            a0 += __shfl_xor_sync(FULLM, a0, off);
            a1 += __shfl_xor_sync(FULLM, a1, off);
            a2 += __shfl_xor_sync(FULLM, a2, off);
            a3 += __shfl_xor_sync(FULLM, a3, off);
        }
        if (lane == 0) {
            h[ob + 0] = fmaxf(a0 + b1[ob + 0], 0.f);
            h[ob + 1] = fmaxf(a1 + b1[ob + 1], 0.f);
            h[ob + 2] = fmaxf(a2 + b1[ob + 2], 0.f);
            h[ob + 3] = fmaxf(a3 + b1[ob + 3], 0.f);
        }
    }
    __syncthreads();

    // layer 2: 8 warps x 2 outputs = block's 16 channels
    const int ob2 = blockIdx.x * 16 + warp * 2;
    float a0 = 0.f, a1 = 0.f;
    #pragma unroll
    for (int j = 0; j < 12; j++) {
        float hv = h[lane + j * 32];
        a0 = fmaf(hv, w2[(ob2 + 0) * 384 + lane + j * 32], a0);
        a1 = fmaf(hv, w2[(ob2 + 1) * 384 + lane + j * 32], a1);
    }
    #pragma unroll
    for (int off = 16; off; off >>= 1) {
        a0 += __shfl_xor_sync(FULLM, a0, off);
        a1 += __shfl_xor_sync(FULLM, a1, off);
    }
    if (lane == 0) {
        #pragma unroll
        for (int u = 0; u < 2; u++) {
            float a = (u == 0 ? a0 : a1) + b2[ob2 + u];
            float gamma = 1.f / (1.f + expf(-a));
            float rms = sqrtf(g_sums[192 + ob2 + u] * (1.0f / 4096.0f) + 1e-6f);
            g_mult[ob2 + u] = scale[ob2 + u] * gamma / rms;
        }
    }
}

// ---------------- convwA: split qkv_w (x g_mult) + proj_w ---------------------
__global__ void convwA_kernel(const float* __restrict__ qkvw, const float* __restrict__ projw) {
    int i4 = blockIdx.x * 256 + threadIdx.x;
    if (i4 < 27648) {                       // qkv_w: 110592 elems
        int idx = i4 * 4;
        float4 v = ((const float4*)qkvw)[i4];
        int m = idx % 192;
        v.x *= g_mult[m]; v.y *= g_mult[m + 1]; v.z *= g_mult[m + 2]; v.w *= g_mult[m + 3];
        split4(v, g_wb, g_wsm, idx);
    } else {                                // proj_w: 36864 elems
        int j = i4 - 27648, idx = j * 4;
        split4(((const float4*)projw)[j], g_wb2, g_ws2, idx);
    }
}

// ---------------- convwB: split mlp_w1 (x g_mult) + mlp_w2, + initout ---------
__global__ void convwB_kernel(const float* __restrict__ w1, const float* __restrict__ w2m,
                              const float* __restrict__ x2, const float* __restrict__ bias,
                              float* __restrict__ out) {
    int i4 = blockIdx.x * 256 + threadIdx.x;
    if (i4 < 36864) {                       // mlp_w1: 147456 elems, fold g_mult
        int idx = i4 * 4;
        float4 v = ((const float4*)w1)[i4];
        int m = idx % 192;
        v.x *= g_mult[m]; v.y *= g_mult[m + 1]; v.z *= g_mult[m + 2]; v.w *= g_mult[m + 3];
        split4(v, g_wb, g_wsm, idx);
    } else if (i4 < 73728) {                // mlp_w2: 147456 elems
        int j = i4 - 36864, idx = j * 4;
        split4(((const float4*)w2m)[j], g_wb2, g_ws2, idx);
    } else {                                // initout: out = x2 + bias (196608 float4)
        int j = i4 - 73728;
        float4 v = ((const float4*)x2)[j];
        float b = bias[j >> 10];
        v.x += b; v.y += b; v.z += b; v.w += b;
        ((float4*)out)[j] = v;
    }
}

// ---------------- GEMM v8: bf16x3 pairs, cp.async 3-stage, ldmatrix.trans -----
template <int CI, int CIFULL, bool BNMAJ, int EPI, bool STATS, int OUTM, bool PAIRS, bool WF32>
__global__ void __launch_bounds__(128)
gemm_kernel(const __nv_bfloat16* __restrict__ Awb, const __nv_bfloat16* __restrict__ Aws,
            const __nv_bfloat16* __restrict__ Bxb, const __nv_bfloat16* __restrict__ Bxs,
            const float* __restrict__ bias, const float* __restrict__ res,
            float* __restrict__ out, __nv_bfloat16* __restrict__ pb,
            __nv_bfloat16* __restrict__ ps, int Co, int N) {
    constexpr int NK = CI / 16;
    constexpr int BW = BNMAJ ? (64 * 12) : (16 * 36);
    __shared__ uint sA[3][2][64 * 12];
    __shared__ uint sB[3][2][BW];

    const int bn = blockIdx.x * 64;
    const int bm = blockIdx.y * 64;
    const int kbase = blockIdx.z * CI;
    const int tid = threadIdx.x;
    const int warp = tid >> 5, lane = tid & 31;
    const int gid = lane >> 2, tig = lane & 3;
    const int wmb = (warp >> 1) * 32;
    const int wnb = (warp & 1) * 32;

    auto stage = [&](int t, int st) {
        const int kk = kbase + t * 16;
        {
            int row = tid >> 1, ch = tid & 1;
            size_t go = (size_t)(bm + row) * CIFULL + kk + ch * 8;
            cp16(smem_u32(&sA[st][0][row * 12 + ch * 4]), Awb + go);
            cp16(smem_u32(&sA[st][1][row * 12 + ch * 4]), Aws + go);
        }
        if (BNMAJ) {
            int row = tid >> 1, ch = tid & 1;
            size_t go = (size_t)(bn + row) * CIFULL + kk + ch * 8;
            cp16(smem_u32(&sB[st][0][row * 12 + ch * 4]), Bxb + go);
            cp16(smem_u32(&sB[st][1][row * 12 + ch * 4]), Bxs + go);
        } else {
            int row = tid >> 3, ch = tid & 7;
            size_t go = (size_t)(kk + row) * N + bn + ch * 8;
            cp16(smem_u32((char*)&sB[st][0][0] + row * 144 + ch * 16), Bxb + go);
            cp16(smem_u32((char*)&sB[st][1][0] + row * 144 + ch * 16), Bxs + go);
        }
        cp_commit();
    };

    float d[2][4][4];
    #pragma unroll
    for (int mt = 0; mt < 2; mt++)
        #pragma unroll
        for (int j = 0; j < 4; j++)
            #pragma unroll
            for (int e = 0; e < 4; e++) d[mt][j][e] = 0.f;

    stage(0, 0);
    stage(1, 1);

    #pragma unroll 1
    for (int t = 0; t < NK; t++) {
        const int st = t % 3;
        if (t == NK - 1) cp_wait<0>(); else cp_wait<1>();
        __syncthreads();

        unsigned Ab[2][4], As[2][4];
        #pragma unroll
        for (int mt = 0; mt < 2; mt++) {
            int m0 = wmb + 16 * mt + gid;
            Ab[mt][0] = sA[st][0][m0 * 12 + tig];
            Ab[mt][1] = sA[st][0][(m0 + 8) * 12 + tig];
            Ab[mt][2] = sA[st][0][m0 * 12 + tig + 4];
            Ab[mt][3] = sA[st][0][(m0 + 8) * 12 + tig + 4];
            As[mt][0] = sA[st][1][m0 * 12 + tig];
            As[mt][1] = sA[st][1][(m0 + 8) * 12 + tig];
            As[mt][2] = sA[st][1][m0 * 12 + tig + 4];
            As[mt][3] = sA[st][1][(m0 + 8) * 12 + tig + 4];
        }
        #pragma unroll
        for (int j = 0; j < 4; j++) {
            unsigned Bb[2], Bs[2];
            if (BNMAJ) {
                int n0 = wnb + 8 * j + gid;
                Bb[0] = sB[st][0][n0 * 12 + tig];
                Bb[1] = sB[st][0][n0 * 12 + tig + 4];
                Bs[0] = sB[st][1][n0 * 12 + tig];
                Bs[1] = sB[st][1][n0 * 12 + tig + 4];
            } else {
                int boff = ((lane & 15) * 72 + wnb + 8 * j) * 2;
                ldsm_x2_trans(Bb[0], Bb[1], smem_u32((char*)&sB[st][0][0] + boff));
                ldsm_x2_trans(Bs[0], Bs[1], smem_u32((char*)&sB[st][1][0] + boff));
            }
            #pragma unroll
            for (int mt = 0; mt < 2; mt++) {
                mma_bf16(d[mt][j], Ab[mt], Bb);
                mma_bf16(d[mt][j], As[mt], Bb);
                mma_bf16(d[mt][j], Ab[mt], Bs);
            }
        }
        if (t + 2 < NK) stage(t + 2, (t + 2) % 3);
    }

    // ---- epilogue ----
    const int gn0 = bn + wnb + 2 * tig;
    #pragma unroll
    for (int mt = 0; mt < 2; mt++) {
        #pragma unroll
        for (int half = 0; half < 2; half++) {
            int m = bm + wmb + 16 * mt + gid + 8 * half;
            float bv = (OUTM == 2) ? 0.f : bias[m];
            float v[8];
            #pragma unroll
            for (int j = 0; j < 4; j++) {
                v[2 * j]     = d[mt][j][2 * half]     + bv;
                v[2 * j + 1] = d[mt][j][2 * half + 1] + bv;
            }
            if (EPI == 1) {
                #pragma unroll
                for (int e = 0; e < 8; e++) {
                    float u = v[e];
                    v[e] = u * 0.5f * (1.f + erff(u * 0.70710678118654752f));
                }
            }
            if (EPI == 2) {
                #pragma unroll
                for (int j = 0; j < 4; j++) {
                    float2 r2 = *(const float2*)&res[(size_t)m * N + gn0 + 8 * j];
                    v[2 * j] += r2.x; v[2 * j + 1] += r2.y;
                }
            }
            if (STATS) {
                float ls = 0.f, ls2 = 0.f;
                #pragma unroll
                for (int e = 0; e < 8; e++) { ls += v[e]; ls2 = fmaf(v[e], v[e], ls2); }
                ls  += __shfl_xor_sync(FULLM, ls, 1);  ls  += __shfl_xor_sync(FULLM, ls, 2);
                ls2 += __shfl_xor_sync(FULLM, ls2, 1); ls2 += __shfl_xor_sync(FULLM, ls2, 2);
                if (tig == 0) {
                    atomicAdd(&g_sums[m], ls);
                    atomicAdd(&g_sums[192 + m], ls2);
                }
            }
            if (PAIRS) {
                #pragma unroll
                for (int j = 0; j < 4; j++)
                    store_pair(pb, ps, (size_t)m * N + gn0 + 8 * j, v[2 * j], v[2 * j + 1]);
            }
            if (OUTM == 2) {
                #pragma unroll
                for (int j = 0; j < 4; j++) {
                    atomicAdd(&out[(size_t)m * N + gn0 + 8 * j],     v[2 * j]);
                    atomicAdd(&out[(size_t)m * N + gn0 + 8 * j + 1], v[2 * j + 1]);
                }
            } else if (OUTM == 1) {
                #pragma unroll
                for (int j = 0; j < 4; j++) {
                    out[(size_t)(gn0 + 8 * j)     * Co + m] = v[2 * j];
                    out[(size_t)(gn0 + 8 * j + 1) * Co + m] = v[2 * j + 1];
                }
            } else if (WF32) {
                #pragma unroll
                for (int j = 0; j < 4; j++)
                    *(float2*)&out[(size_t)m * N + gn0 + 8 * j] = make_float2(v[2 * j], v[2 * j + 1]);
            }
        }
    }
}

// ---------------- 3D neighborhood attention (tiled, fp16 K/V in smem) ---------
// Block (0,0) also zeroes ALL 384 g_sums entries (strided: block has 256 thr).
// Safe point: after gamma-A reads, before proj's STATS atomics.
__global__ void __launch_bounds__(256) attn_kernel(const float* __restrict__ qkv,
                                                   __nv_bfloat16* __restrict__ obb,
                                                   __nv_bfloat16* __restrict__ obs) {
    extern __shared__ __align__(16) half2 sKV[];   // sK[8192] then sV[8192]
    half2* sK = sKV;
    half2* sV = sKV + 8192;

    const int tile = blockIdx.x, head = blockIdx.y;
    const int tid = threadIdx.x;
    if (tile == 0 && head == 0) {
        for (int i = tid; i < 384; i += 256) g_sums[i] = 0.f;   // FIX: cover all 384
    }

    const int Td = ((tile >> 4) & 3) * 4, Th = ((tile >> 2) & 3) * 4, Tw = (tile & 3) * 4;
    const int Bd = min(max(Td - 2, 0), 8);
    const int Bh = min(max(Th - 2, 0), 8);
    const int Bw = min(max(Tw - 2, 0), 8);

    #pragma unroll
    for (int it = 0; it < 16; it++) {
        int i = tid + it * 256;
        int row = i >> 3, g = i & 7;
        int rd = row >> 6, rh = (row >> 3) & 7, rw = row & 7;
        int gpos = ((Bd + rd) << 8) + ((Bh + rh) << 4) + (Bw + rw);
        const float* base = qkv + (size_t)gpos * 576 + head * 32 + g * 4;
        float4 kv = *(const float4*)(base + 192);
        float4 vv = *(const float4*)(base + 384);
        sK[row * 16 + g * 2]     = __floats2half2_rn(kv.x, kv.y);
        sK[row * 16 + g * 2 + 1] = __floats2half2_rn(kv.z, kv.w);
        sV[row * 16 + g * 2]     = __floats2half2_rn(vv.x, vv.y);
        sV[row * 16 + g * 2 + 1] = __floats2half2_rn(vv.z, vv.w);
    }

    const int quarter = tid & 3, vox = tid >> 2;
    const int aw = vox & 3, ah = (vox >> 2) & 3, ad = vox >> 4;
    const int vd = Td + ad, vh = Th + ah, vw = Tw + aw;
    const int gv = (vd << 8) + (vh << 4) + vw;
    const int ld = min(max(vd - 2, 0), 11) - Bd;
    const int lh = min(max(vh - 2, 0), 11) - Bh;
    const int lw = min(max(vw - 2, 0), 11) - Bw;
    const int rbase = ld * 64 + lh * 8 + lw;
    const int lane = tid & 31;

    float q[8];
    {
        const float* qp = qkv + (size_t)gv * 576 + head * 32 + quarter * 8;
        #pragma unroll
        for (int c = 0; c < 8; c++) q[c] = qp[c] * 0.17677669529663687f;
    }
    __syncthreads();

    float sc[32];
    #pragma unroll
    for (int i = 0; i < 32; i++) sc[i] = -1e30f;

    #pragma unroll
    for (int j = 0; j < 125; j++) {
        const int a = j / 25, b = (j / 5) % 5, c5 = j % 5;
        int row = rbase + a * 64 + b * 8 + c5;
        uint4 kk = *(const uint4*)(sK + row * 16 + quarter * 4);
        float2 f0 = __half22float2(*reinterpret_cast<half2*>(&kk.x));
        float2 f1 = __half22float2(*reinterpret_cast<half2*>(&kk.y));
        float2 f2 = __half22float2(*reinterpret_cast<half2*>(&kk.z));
        float2 f3 = __half22float2(*reinterpret_cast<half2*>(&kk.w));
        float p = q[0] * f0.x;
        p = fmaf(q[1], f0.y, p); p = fmaf(q[2], f1.x, p); p = fmaf(q[3], f1.y, p);
        p = fmaf(q[4], f2.x, p); p = fmaf(q[5], f2.y, p);
        p = fmaf(q[6], f3.x, p); p = fmaf(q[7], f3.y, p);
        p += __shfl_xor_sync(FULLM, p, 1);
        p += __shfl_xor_sync(FULLM, p, 2);
        if ((j & 3) == quarter) sc[j >> 2] = p;
    }

    float mx = -1e30f;
    #pragma unroll
    for (int i = 0; i < 32; i++) mx = fmaxf(mx, sc[i]);
    mx = fmaxf(mx, __shfl_xor_sync(FULLM, mx, 1));
    mx = fmaxf(mx, __shfl_xor_sync(FULLM, mx, 2));
    float tot = 0.f;
    #pragma unroll
    for (int i = 0; i < 32; i++) { sc[i] = __expf(sc[i] - mx); tot += sc[i]; }
    tot += __shfl_xor_sync(FULLM, tot, 1);
    tot += __shfl_xor_sync(FULLM, tot, 2);
    float inv = 1.f / tot;

    float o8[8] = {0.f, 0.f, 0.f, 0.f, 0.f, 0.f, 0.f, 0.f};
    #pragma unroll
    for (int j = 0; j < 125; j++) {
        const int a = j / 25, b = (j / 5) % 5, c5 = j % 5;
        float p = __shfl_sync(FULLM, sc[j >> 2], (lane & ~3) | (j & 3));
        int row = rbase + a * 64 + b * 8 + c5;
        uint4 vvp = *(const uint4*)(sV + row * 16 + quarter * 4);
        float2 f0 = __half22float2(*reinterpret_cast<half2*>(&vvp.x));
        float2 f1 = __half22float2(*reinterpret_cast<half2*>(&vvp.y));
        float2 f2 = __half22float2(*reinterpret_cast<half2*>(&vvp.z));
        float2 f3 = __half22float2(*reinterpret_cast<half2*>(&vvp.w));
        o8[0] = fmaf(p, f0.x, o8[0]); o8[1] = fmaf(p, f0.y, o8[1]);
        o8[2] = fmaf(p, f1.x, o8[2]); o8[3] = fmaf(p, f1.y, o8[3]);
        o8[4] = fmaf(p, f2.x, o8[4]); o8[5] = fmaf(p, f2.y, o8[5]);
        o8[6] = fmaf(p, f3.x, o8[6]); o8[7] = fmaf(p, f3.y, o8[7]);
    }
    size_t ob0 = (size_t)gv * 192 + head * 32 + quarter * 8;
    #pragma unroll
    for (int c = 0; c < 4; c++)
        store_pair(obb, obs, ob0 + 2 * c, o8[2 * c] * inv, o8[2 * c + 1] * inv);
}

// ---------------- orchestration ----------------------------------------------
extern "C" void kernel_launch(void* const* d_in, const int* in_sizes, int n_in,
                              void* d_out, int out_size) {
    const float* x      = (const float*)d_in[0];
    const float* scale1 = (const float*)d_in[1];
    const float* n1_w1  = (const float*)d_in[2];
    const float* n1_b1  = (const float*)d_in[3];
    const float* n1_w2  = (const float*)d_in[4];
    const float* n1_b2  = (const float*)d_in[5];
    const float* qkv_w  = (const float*)d_in[6];
    const float* qkv_b  = (const float*)d_in[7];
    const float* proj_w = (const float*)d_in[8];
    const float* proj_b = (const float*)d_in[9];
    const float* scale2 = (const float*)d_in[10];
    const float* n2_w1  = (const float*)d_in[11];
    const float* n2_b1  = (const float*)d_in[12];
    const float* n2_w2  = (const float*)d_in[13];
    const float* n2_b2  = (const float*)d_in[14];
    const float* mlp_w1 = (const float*)d_in[15];
    const float* mlp_b1 = (const float*)d_in[16];
    const float* mlp_w2 = (const float*)d_in[17];
    const float* mlp_b2 = (const float*)d_in[18];
    float* out = (float*)d_out;

    float *qkv, *x2;
    __nv_bfloat16 *wb, *wsm, *wb2, *ws2, *xb, *xs, *obb, *obs, *x2b, *x2s, *mbb, *mbs;
    cudaGetSymbolAddress((void**)&qkv, g_qkv);
    cudaGetSymbolAddress((void**)&x2,  g_x2);
    cudaGetSymbolAddress((void**)&wb,  g_wb);
    cudaGetSymbolAddress((void**)&wsm, g_wsm);
    cudaGetSymbolAddress((void**)&wb2, g_wb2);
    cudaGetSymbolAddress((void**)&ws2, g_ws2);
    cudaGetSymbolAddress((void**)&xb,  g_xb);
    cudaGetSymbolAddress((void**)&xs,  g_xs);
    cudaGetSymbolAddress((void**)&obb, g_obb);
    cudaGetSymbolAddress((void**)&obs, g_obs);
    cudaGetSymbolAddress((void**)&x2b, g_x2b);
    cudaGetSymbolAddress((void**)&x2s, g_x2s);
    cudaGetSymbolAddress((void**)&mbb, g_mbb);
    cudaGetSymbolAddress((void**)&mbs, g_mbs);

    cudaFuncSetAttribute(attn_kernel, cudaFuncAttributeMaxDynamicSharedMemorySize, 65536);

    // ---- stage A ----
    colstats_kernel<<<192, 256>>>(x, xb, xs);                        // 1
    gamma_kernel<<<12, 256>>>(n1_w1, n1_b1, n1_w2, n1_b2, scale1);   // 2
    convwA_kernel<<<144, 256>>>(qkv_w, proj_w);                      // 3

    // qkv: (576,192)@(192,4096) -> (4096,576) fp32 pos-major        // 4 (profiled)
    gemm_kernel<192, 192, false, 0, false, 1, false, false><<<dim3(64, 9), 128>>>(
        wb, wsm, xb, xs, qkv_b, nullptr, qkv, nullptr, nullptr, 576, NPOS);

    // attention -> ob bf16 pairs (N,C); zeroes g_sums               // 5
    attn_kernel<<<dim3(64, 6), 256, 65536>>>(qkv, obb, obs);

    // proj + residual + stage-B stats; writes x2 fp32 + bf16 pairs  // 6
    gemm_kernel<192, 192, true, 2, true, 0, true, true><<<dim3(64, 3), 128>>>(
        wb2, ws2, obb, obs, proj_b, x, x2, x2b, x2s, 192, NPOS);

    // ---- stage B ----
    gamma_kernel<<<12, 256>>>(n2_w1, n2_b1, n2_w2, n2_b2, scale2);   // 7
    convwB_kernel<<<1056, 256>>>(mlp_w1, mlp_w2, x2, mlp_b2, out);   // 8 (also initout)

    // mlp1 + gelu -> mb bf16 pairs only                             // 9
    gemm_kernel<192, 192, false, 1, false, 0, true, false><<<dim3(64, 12), 128>>>(
        wb, wsm, x2b, x2s, mlp_b1, nullptr, nullptr, mbb, mbs, 768, NPOS);

    // mlp2 split-K x4 atomic-accumulate into pre-initialized out    // 10
    gemm_kernel<192, 768, false, 0, false, 2, false, false><<<dim3(64, 3, 4), 128>>>(
        wb2, ws2, mbb, mbs, mlp_b2, nullptr, out, nullptr, nullptr, 192, NPOS);
}

// round 12
// speedup vs baseline: 1.0778x; 1.0778x over previous
#include <cuda_runtime.h>
#include <cuda_fp16.h>
#include <cuda_bf16.h>
#include <math.h>

#define NPOS 4096
#define FULLM 0xffffffffu

// ---------------- scratch (static device globals; no allocation) -------------
__device__ __half g_qkvh[NPOS * 576];          // (pos, 576) pos-major fp16
__device__ float g_x2 [192 * NPOS];            // (C, pos) fp32
__device__ float g_sums[2 * 192];              // per-channel sum / sumsq
__device__ float g_mult[192];                  // scale*gamma/rms
__device__ float g_h[384];                     // norm-MLP hidden
// bf16 big/small pairs
__device__ __nv_bfloat16 g_wb [768 * 192],  g_wsm[768 * 192];    // W bank 0 (qkv, then mlp_w1)
__device__ __nv_bfloat16 g_wb2[192 * 768],  g_ws2[192 * 768];    // W bank 1 (proj, then mlp_w2)
__device__ __nv_bfloat16 g_xb [192 * NPOS], g_xs [192 * NPOS];   // x pairs (C,N)
__device__ __nv_bfloat16 g_obb[NPOS * 192], g_obs[NPOS * 192];   // attn out pairs (N,C)
__device__ __nv_bfloat16 g_x2b[192 * NPOS], g_x2s[192 * NPOS];   // x2 pairs (C,N)
__device__ __nv_bfloat16 g_mbb[768 * NPOS], g_mbs[768 * NPOS];   // mlp hidden pairs (C,N)

// ---------------- helpers -----------------------------------------------------
__device__ __forceinline__ unsigned smem_u32(const void* p) {
    return (unsigned)__cvta_generic_to_shared(p);
}
__device__ __forceinline__ void cp16(unsigned dst, const void* src) {
    asm volatile("cp.async.cg.shared.global [%0], [%1], 16;" :: "r"(dst), "l"(src));
}
__device__ __forceinline__ void cp_commit() { asm volatile("cp.async.commit_group;"); }
template <int W> __device__ __forceinline__ void cp_wait() {
    asm volatile("cp.async.wait_group %0;" :: "n"(W));
}
__device__ __forceinline__ void mma_bf16(float* d, const unsigned* a, const unsigned* b) {
    asm volatile(
        "mma.sync.aligned.m16n8k16.row.col.f32.bf16.bf16.f32 "
        "{%0,%1,%2,%3},{%4,%5,%6,%7},{%8,%9},{%0,%1,%2,%3};"
        : "+f"(d[0]), "+f"(d[1]), "+f"(d[2]), "+f"(d[3])
        : "r"(a[0]), "r"(a[1]), "r"(a[2]), "r"(a[3]), "r"(b[0]), "r"(b[1]));
}
__device__ __forceinline__ void ldsm_x2_trans(unsigned& r0, unsigned& r1, unsigned addr) {
    asm volatile("ldmatrix.sync.aligned.m8n8.x2.trans.shared.b16 {%0,%1}, [%2];"
                 : "=r"(r0), "=r"(r1) : "r"(addr));
}
__device__ __forceinline__ void store_pair(__nv_bfloat16* pb, __nv_bfloat16* ps,
                                           size_t idx, float v0, float v1) {
    __nv_bfloat16 b0 = __float2bfloat16_rn(v0), b1 = __float2bfloat16_rn(v1);
    __nv_bfloat16 s0 = __float2bfloat16_rn(v0 - __bfloat162float(b0));
    __nv_bfloat16 s1 = __float2bfloat16_rn(v1 - __bfloat162float(b1));
    *(__nv_bfloat162*)(pb + idx) = __halves2bfloat162(b0, b1);
    *(__nv_bfloat162*)(ps + idx) = __halves2bfloat162(s0, s1);
}
__device__ __forceinline__ void split4(float4 v, __nv_bfloat16* db, __nv_bfloat16* ds, int idx) {
    __nv_bfloat16 b0 = __float2bfloat16_rn(v.x), b1 = __float2bfloat16_rn(v.y);
    __nv_bfloat16 b2 = __float2bfloat16_rn(v.z), b3 = __float2bfloat16_rn(v.w);
    *(__nv_bfloat162*)(db + idx)     = __halves2bfloat162(b0, b1);
    *(__nv_bfloat162*)(db + idx + 2) = __halves2bfloat162(b2, b3);
    *(__nv_bfloat162*)(ds + idx) = __halves2bfloat162(
        __float2bfloat16_rn(v.x - __bfloat162float(b0)),
        __float2bfloat16_rn(v.y - __bfloat162float(b1)));
    *(__nv_bfloat162*)(ds + idx + 2) = __halves2bfloat162(
        __float2bfloat16_rn(v.z - __bfloat162float(b2)),
        __float2bfloat16_rn(v.w - __bfloat162float(b3)));
}

// ---------------- per-channel stats over x + bf16 pair conversion -------------
__global__ void colstats_kernel(const float* __restrict__ x,
                                __nv_bfloat16* __restrict__ xb,
                                __nv_bfloat16* __restrict__ xs) {
    int c = blockIdx.x;
    const float* p = x + c * NPOS;
    float s = 0.f, s2 = 0.f;
    for (int i = threadIdx.x; i < NPOS; i += 256) {
        float v = p[i];
        s += v;
        s2 = fmaf(v, v, s2);
        __nv_bfloat16 b = __float2bfloat16_rn(v);
        xb[c * NPOS + i] = b;
        xs[c * NPOS + i] = __float2bfloat16_rn(v - __bfloat162float(b));
    }
    __shared__ float sh0[256], sh1[256];
    sh0[threadIdx.x] = s; sh1[threadIdx.x] = s2;
    __syncthreads();
    for (int o = 128; o > 0; o >>= 1) {
        if (threadIdx.x < o) {
            sh0[threadIdx.x] += sh0[threadIdx.x + o];
            sh1[threadIdx.x] += sh1[threadIdx.x + o];
        }
        __syncthreads();
    }
    if (threadIdx.x == 0) {
        g_sums[c]       = sh0[0];
        g_sums[192 + c] = sh1[0];
    }
}

// ---------------- norm-MLP layer 1 (R9 split version) -------------------------
__global__ void gamma1_kernel(const float* __restrict__ w1, const float* __restrict__ b1) {
    const int warp = threadIdx.x >> 5, lane = threadIdx.x & 31;
    const int ob = blockIdx.x * 16 + warp * 4;
    float a0 = 0.f, a1 = 0.f, a2 = 0.f, a3 = 0.f;
    #pragma unroll
    for (int j = 0; j < 6; j++) {
        float sv = g_sums[lane + j * 32] * (1.0f / 4096.0f);
        a0 = fmaf(sv, w1[(ob + 0) * 192 + lane + j * 32], a0);
        a1 = fmaf(sv, w1[(ob + 1) * 192 + lane + j * 32], a1);
        a2 = fmaf(sv, w1[(ob + 2) * 192 + lane + j * 32], a2);
        a3 = fmaf(sv, w1[(ob + 3) * 192 + lane + j * 32], a3);
    }
    #pragma unroll
    for (int off = 16; off; off >>= 1) {
        a0 += __shfl_xor_sync(FULLM, a0, off);
        a1 += __shfl_xor_sync(FULLM, a1, off);
        a2 += __shfl_xor_sync(FULLM, a2, off);
        a3 += __shfl_xor_sync(FULLM, a3, off);
    }
    if (lane == 0) {
        g_h[ob + 0] = fmaxf(a0 + b1[ob + 0], 0.f);
        g_h[ob + 1] = fmaxf(a1 + b1[ob + 1], 0.f);
        g_h[ob + 2] = fmaxf(a2 + b1[ob + 2], 0.f);
        g_h[ob + 3] = fmaxf(a3 + b1[ob + 3], 0.f);
    }
}

// ---------------- norm-MLP layer 2 -> g_mult; zeroes g_sums -------------------
__global__ void gamma2_kernel(const float* __restrict__ w2, const float* __restrict__ b2,
                              const float* __restrict__ scale) {
    const int warp = threadIdx.x >> 5, lane = threadIdx.x & 31;
    const int ob = blockIdx.x * 16 + warp * 4;
    float a0 = 0.f, a1 = 0.f, a2 = 0.f, a3 = 0.f;
    #pragma unroll
    for (int j = 0; j < 12; j++) {
        float hv = g_h[lane + j * 32];
        a0 = fmaf(hv, w2[(ob + 0) * 384 + lane + j * 32], a0);
        a1 = fmaf(hv, w2[(ob + 1) * 384 + lane + j * 32], a1);
        a2 = fmaf(hv, w2[(ob + 2) * 384 + lane + j * 32], a2);
        a3 = fmaf(hv, w2[(ob + 3) * 384 + lane + j * 32], a3);
    }
    #pragma unroll
    for (int off = 16; off; off >>= 1) {
        a0 += __shfl_xor_sync(FULLM, a0, off);
        a1 += __shfl_xor_sync(FULLM, a1, off);
        a2 += __shfl_xor_sync(FULLM, a2, off);
        a3 += __shfl_xor_sync(FULLM, a3, off);
    }
    if (lane == 0) {
        #pragma unroll
        for (int u = 0; u < 4; u++) {
            float a = (u == 0 ? a0 : u == 1 ? a1 : u == 2 ? a2 : a3) + b2[ob + u];
            float gamma = 1.f / (1.f + expf(-a));
            float rms = sqrtf(g_sums[192 + ob + u] * (1.0f / 4096.0f) + 1e-6f);
            g_mult[ob + u] = scale[ob + u] * gamma / rms;
            g_sums[ob + u] = 0.f;
            g_sums[192 + ob + u] = 0.f;
        }
    }
}

// ---------------- convwA: split qkv_w (x g_mult) + proj_w ---------------------
__global__ void convwA_kernel(const float* __restrict__ qkvw, const float* __restrict__ projw) {
    int i4 = blockIdx.x * 256 + threadIdx.x;
    if (i4 < 27648) {                       // qkv_w: 110592 elems
        int idx = i4 * 4;
        float4 v = ((const float4*)qkvw)[i4];
        int m = idx % 192;
        v.x *= g_mult[m]; v.y *= g_mult[m + 1]; v.z *= g_mult[m + 2]; v.w *= g_mult[m + 3];
        split4(v, g_wb, g_wsm, idx);
    } else {                                // proj_w: 36864 elems
        int j = i4 - 27648, idx = j * 4;
        split4(((const float4*)projw)[j], g_wb2, g_ws2, idx);
    }
}

// ---------------- convwB: split mlp_w1 (x g_mult) + mlp_w2, + initout ---------
__global__ void convwB_kernel(const float* __restrict__ w1, const float* __restrict__ w2m,
                              const float* __restrict__ x2, const float* __restrict__ bias,
                              float* __restrict__ out) {
    int i4 = blockIdx.x * 256 + threadIdx.x;
    if (i4 < 36864) {                       // mlp_w1: fold g_mult
        int idx = i4 * 4;
        float4 v = ((const float4*)w1)[i4];
        int m = idx % 192;
        v.x *= g_mult[m]; v.y *= g_mult[m + 1]; v.z *= g_mult[m + 2]; v.w *= g_mult[m + 3];
        split4(v, g_wb, g_wsm, idx);
    } else if (i4 < 73728) {                // mlp_w2
        int j = i4 - 36864, idx = j * 4;
        split4(((const float4*)w2m)[j], g_wb2, g_ws2, idx);
    } else {                                // initout: out = x2 + bias
        int j = i4 - 73728;
        float4 v = ((const float4*)x2)[j];
        float b = bias[j >> 10];
        v.x += b; v.y += b; v.z += b; v.w += b;
        ((float4*)out)[j] = v;
    }
}

// ---------------- GEMM v9: bf16x3 pairs, cp.async 3-stage ---------------------
// OUTM: 0 fp32 (Co,N) if WF32, 2 atomicAdd (Co,N), 3 fp16 (N,Co) smem-staged.
template <int CI, int CIFULL, bool BNMAJ, int EPI, bool STATS, int OUTM, bool PAIRS, bool WF32>
__global__ void __launch_bounds__(128)
gemm_kernel(const __nv_bfloat16* __restrict__ Awb, const __nv_bfloat16* __restrict__ Aws,
            const __nv_bfloat16* __restrict__ Bxb, const __nv_bfloat16* __restrict__ Bxs,
            const float* __restrict__ bias, const float* __restrict__ res,
            float* __restrict__ out, __nv_bfloat16* __restrict__ pb,
            __nv_bfloat16* __restrict__ ps, int Co, int N) {
    constexpr int NK = CI / 16;
    constexpr int BW = BNMAJ ? (64 * 12) : (16 * 36);
    __shared__ uint sA[3][2][64 * 12];
    __shared__ uint sB[3][2][BW];
    __shared__ __half sT[(OUTM == 3) ? 64 * 72 : 8];   // transpose staging (stride 72)

    const int bn = blockIdx.x * 64;
    const int bm = blockIdx.y * 64;
    const int kbase = blockIdx.z * CI;
    const int tid = threadIdx.x;
    const int warp = tid >> 5, lane = tid & 31;
    const int gid = lane >> 2, tig = lane & 3;
    const int wmb = (warp >> 1) * 32;
    const int wnb = (warp & 1) * 32;

    auto stage = [&](int t, int st) {
        const int kk = kbase + t * 16;
        {
            int row = tid >> 1, ch = tid & 1;
            size_t go = (size_t)(bm + row) * CIFULL + kk + ch * 8;
            cp16(smem_u32(&sA[st][0][row * 12 + ch * 4]), Awb + go);
            cp16(smem_u32(&sA[st][1][row * 12 + ch * 4]), Aws + go);
        }
        if (BNMAJ) {
            int row = tid >> 1, ch = tid & 1;
            size_t go = (size_t)(bn + row) * CIFULL + kk + ch * 8;
            cp16(smem_u32(&sB[st][0][row * 12 + ch * 4]), Bxb + go);
            cp16(smem_u32(&sB[st][1][row * 12 + ch * 4]), Bxs + go);
        } else {
            int row = tid >> 3, ch = tid & 7;
            size_t go = (size_t)(kk + row) * N + bn + ch * 8;
            cp16(smem_u32((char*)&sB[st][0][0] + row * 144 + ch * 16), Bxb + go);
            cp16(smem_u32((char*)&sB[st][1][0] + row * 144 + ch * 16), Bxs + go);
        }
        cp_commit();
    };

    float d[2][4][4];
    #pragma unroll
    for (int mt = 0; mt < 2; mt++)
        #pragma unroll
        for (int j = 0; j < 4; j++)
            #pragma unroll
            for (int e = 0; e < 4; e++) d[mt][j][e] = 0.f;

    stage(0, 0);
    stage(1, 1);

    #pragma unroll 1
    for (int t = 0; t < NK; t++) {
        const int st = t % 3;
        if (t == NK - 1) cp_wait<0>(); else cp_wait<1>();
        __syncthreads();

        unsigned Ab[2][4], As[2][4];
        #pragma unroll
        for (int mt = 0; mt < 2; mt++) {
            int m0 = wmb + 16 * mt + gid;
            Ab[mt][0] = sA[st][0][m0 * 12 + tig];
            Ab[mt][1] = sA[st][0][(m0 + 8) * 12 + tig];
            Ab[mt][2] = sA[st][0][m0 * 12 + tig + 4];
            Ab[mt][3] = sA[st][0][(m0 + 8) * 12 + tig + 4];
            As[mt][0] = sA[st][1][m0 * 12 + tig];
            As[mt][1] = sA[st][1][(m0 + 8) * 12 + tig];
            As[mt][2] = sA[st][1][m0 * 12 + tig + 4];
            As[mt][3] = sA[st][1][(m0 + 8) * 12 + tig + 4];
        }
        #pragma unroll
        for (int j = 0; j < 4; j++) {
            unsigned Bb[2], Bs[2];
            if (BNMAJ) {
                int n0 = wnb + 8 * j + gid;
                Bb[0] = sB[st][0][n0 * 12 + tig];
                Bb[1] = sB[st][0][n0 * 12 + tig + 4];
                Bs[0] = sB[st][1][n0 * 12 + tig];
                Bs[1] = sB[st][1][n0 * 12 + tig + 4];
            } else {
                int boff = ((lane & 15) * 72 + wnb + 8 * j) * 2;
                ldsm_x2_trans(Bb[0], Bb[1], smem_u32((char*)&sB[st][0][0] + boff));
                ldsm_x2_trans(Bs[0], Bs[1], smem_u32((char*)&sB[st][1][0] + boff));
            }
            #pragma unroll
            for (int mt = 0; mt < 2; mt++) {
                mma_bf16(d[mt][j], Ab[mt], Bb);
                mma_bf16(d[mt][j], As[mt], Bb);
                mma_bf16(d[mt][j], Ab[mt], Bs);
            }
        }
        if (t + 2 < NK) stage(t + 2, (t + 2) % 3);
    }

    // ---- epilogue ----
    const int gn0 = bn + wnb + 2 * tig;
    #pragma unroll
    for (int mt = 0; mt < 2; mt++) {
        #pragma unroll
        for (int half = 0; half < 2; half++) {
            int m = bm + wmb + 16 * mt + gid + 8 * half;
            float bv = (OUTM == 2) ? 0.f : bias[m];
            float v[8];
            #pragma unroll
            for (int j = 0; j < 4; j++) {
                v[2 * j]     = d[mt][j][2 * half]     + bv;
                v[2 * j + 1] = d[mt][j][2 * half + 1] + bv;
            }
            if (EPI == 1) {
                #pragma unroll
                for (int e = 0; e < 8; e++) {
                    float u = v[e];
                    v[e] = u * 0.5f * (1.f + erff(u * 0.70710678118654752f));
                }
            }
            if (EPI == 2) {
                #pragma unroll
                for (int j = 0; j < 4; j++) {
                    float2 r2 = *(const float2*)&res[(size_t)m * N + gn0 + 8 * j];
                    v[2 * j] += r2.x; v[2 * j + 1] += r2.y;
                }
            }
            if (STATS) {
                float ls = 0.f, ls2 = 0.f;
                #pragma unroll
                for (int e = 0; e < 8; e++) { ls += v[e]; ls2 = fmaf(v[e], v[e], ls2); }
                ls  += __shfl_xor_sync(FULLM, ls, 1);  ls  += __shfl_xor_sync(FULLM, ls, 2);
                ls2 += __shfl_xor_sync(FULLM, ls2, 1); ls2 += __shfl_xor_sync(FULLM, ls2, 2);
                if (tig == 0) {
                    atomicAdd(&g_sums[m], ls);
                    atomicAdd(&g_sums[192 + m], ls2);
                }
            }
            if (PAIRS) {
                #pragma unroll
                for (int j = 0; j < 4; j++)
                    store_pair(pb, ps, (size_t)m * N + gn0 + 8 * j, v[2 * j], v[2 * j + 1]);
            }
            if (OUTM == 3) {
                int ml = wmb + 16 * mt + gid + 8 * half;   // local m
                #pragma unroll
                for (int j = 0; j < 4; j++) {
                    int nl = wnb + 2 * tig + 8 * j;
                    sT[nl * 72 + ml]       = __float2half(v[2 * j]);
                    sT[(nl + 1) * 72 + ml] = __float2half(v[2 * j + 1]);
                }
            } else if (OUTM == 2) {
                #pragma unroll
                for (int j = 0; j < 4; j++) {
                    atomicAdd(&out[(size_t)m * N + gn0 + 8 * j],     v[2 * j]);
                    atomicAdd(&out[(size_t)m * N + gn0 + 8 * j + 1], v[2 * j + 1]);
                }
            } else if (WF32) {
                #pragma unroll
                for (int j = 0; j < 4; j++)
                    *(float2*)&out[(size_t)m * N + gn0 + 8 * j] = make_float2(v[2 * j], v[2 * j + 1]);
            }
        }
    }
    if (OUTM == 3) {
        __syncthreads();
        __half* oh = (__half*)out;
        #pragma unroll
        for (int i = 0; i < 4; i++) {
            int idx = tid + i * 128;              // 512 16B chunks
            int row = idx >> 3, ch = idx & 7;
            *(uint4*)(oh + (size_t)(bn + row) * Co + bm + ch * 8) =
                *(const uint4*)(sT + row * 72 + ch * 8);
        }
    }
}

// ---------------- 3D neighborhood attention (fp16 qkv input) ------------------
__global__ void __launch_bounds__(256) attn_kernel(const __half* __restrict__ qkvh,
                                                   __nv_bfloat16* __restrict__ obb,
                                                   __nv_bfloat16* __restrict__ obs) {
    extern __shared__ __align__(16) half2 sKV[];   // sK[8192] then sV[8192]
    half2* sK = sKV;
    half2* sV = sKV + 8192;

    const int tile = blockIdx.x, head = blockIdx.y;
    const int tid = threadIdx.x;

    const int Td = ((tile >> 4) & 3) * 4, Th = ((tile >> 2) & 3) * 4, Tw = (tile & 3) * 4;
    const int Bd = min(max(Td - 2, 0), 8);
    const int Bh = min(max(Th - 2, 0), 8);
    const int Bw = min(max(Tw - 2, 0), 8);

    // ---- stage K and V: pure uint4 copies (8 channels each) ----
    #pragma unroll
    for (int it = 0; it < 16; it++) {
        int i = tid + it * 256;                 // 4096 chunks
        int row = i >> 3, g = i & 7;            // g: 0-3 K chunks, 4-7 V chunks
        int rd = row >> 6, rh = (row >> 3) & 7, rw = row & 7;
        int gpos = ((Bd + rd) << 8) + ((Bh + rh) << 4) + (Bw + rw);
        int mat = g >> 2, c = g & 3;
        const __half* src = qkvh + (size_t)gpos * 576 + 192 + 192 * mat + head * 32 + c * 8;
        half2* dst = (mat ? sV : sK) + row * 16 + c * 4;
        *(uint4*)dst = *(const uint4*)src;
    }

    const int quarter = tid & 3, vox = tid >> 2;
    const int aw = vox & 3, ah = (vox >> 2) & 3, ad = vox >> 4;
    const int vd = Td + ad, vh = Th + ah, vw = Tw + aw;
    const int gv = (vd << 8) + (vh << 4) + vw;
    const int ld = min(max(vd - 2, 0), 11) - Bd;
    const int lh = min(max(vh - 2, 0), 11) - Bh;
    const int lw = min(max(vw - 2, 0), 11) - Bw;
    const int rbase = ld * 64 + lh * 8 + lw;
    const int lane = tid & 31;

    float q[8];
    {
        const __half* qp = qkvh + (size_t)gv * 576 + head * 32 + quarter * 8;
        uint4 qq = *(const uint4*)qp;
        const half2* qh = (const half2*)&qq;
        #pragma unroll
        for (int c = 0; c < 4; c++) {
            float2 f = __half22float2(qh[c]);
            q[2 * c]     = f.x * 0.17677669529663687f;
            q[2 * c + 1] = f.y * 0.17677669529663687f;
        }
    }
    __syncthreads();

    float sc[32];
    #pragma unroll
    for (int i = 0; i < 32; i++) sc[i] = -1e30f;

    #pragma unroll
    for (int j = 0; j < 125; j++) {
        const int a = j / 25, b = (j / 5) % 5, c5 = j % 5;
        int row = rbase + a * 64 + b * 8 + c5;
        uint4 kk = *(const uint4*)(sK + row * 16 + quarter * 4);
        float2 f0 = __half22float2(*reinterpret_cast<half2*>(&kk.x));
        float2 f1 = __half22float2(*reinterpret_cast<half2*>(&kk.y));
        float2 f2 = __half22float2(*reinterpret_cast<half2*>(&kk.z));
        float2 f3 = __half22float2(*reinterpret_cast<half2*>(&kk.w));
        float p = q[0] * f0.x;
        p = fmaf(q[1], f0.y, p); p = fmaf(q[2], f1.x, p); p = fmaf(q[3], f1.y, p);
        p = fmaf(q[4], f2.x, p); p = fmaf(q[5], f2.y, p);
        p = fmaf(q[6], f3.x, p); p = fmaf(q[7], f3.y, p);
        p += __shfl_xor_sync(FULLM, p, 1);
        p += __shfl_xor_sync(FULLM, p, 2);
        if ((j & 3) == quarter) sc[j >> 2] = p;
    }

    float mx = -1e30f;
    #pragma unroll
    for (int i = 0; i < 32; i++) mx = fmaxf(mx, sc[i]);
    mx = fmaxf(mx, __shfl_xor_sync(FULLM, mx, 1));
    mx = fmaxf(mx, __shfl_xor_sync(FULLM, mx, 2));
    float tot = 0.f;
    #pragma unroll
    for (int i = 0; i < 32; i++) { sc[i] = __expf(sc[i] - mx); tot += sc[i]; }
    tot += __shfl_xor_sync(FULLM, tot, 1);
    tot += __shfl_xor_sync(FULLM, tot, 2);
    float inv = 1.f / tot;

    float o8[8] = {0.f, 0.f, 0.f, 0.f, 0.f, 0.f, 0.f, 0.f};
    #pragma unroll
    for (int j = 0; j < 125; j++) {
        const int a = j / 25, b = (j / 5) % 5, c5 = j % 5;
        float p = __shfl_sync(FULLM, sc[j >> 2], (lane & ~3) | (j & 3));
        int row = rbase + a * 64 + b * 8 + c5;
        uint4 vvp = *(const uint4*)(sV + row * 16 + quarter * 4);
        float2 f0 = __half22float2(*reinterpret_cast<half2*>(&vvp.x));
        float2 f1 = __half22float2(*reinterpret_cast<half2*>(&vvp.y));
        float2 f2 = __half22float2(*reinterpret_cast<half2*>(&vvp.z));
        float2 f3 = __half22float2(*reinterpret_cast<half2*>(&vvp.w));
        o8[0] = fmaf(p, f0.x, o8[0]); o8[1] = fmaf(p, f0.y, o8[1]);
        o8[2] = fmaf(p, f1.x, o8[2]); o8[3] = fmaf(p, f1.y, o8[3]);
        o8[4] = fmaf(p, f2.x, o8[4]); o8[5] = fmaf(p, f2.y, o8[5]);
        o8[6] = fmaf(p, f3.x, o8[6]); o8[7] = fmaf(p, f3.y, o8[7]);
    }
    size_t ob0 = (size_t)gv * 192 + head * 32 + quarter * 8;
    #pragma unroll
    for (int c = 0; c < 4; c++)
        store_pair(obb, obs, ob0 + 2 * c, o8[2 * c] * inv, o8[2 * c + 1] * inv);
}

// ---------------- orchestration ----------------------------------------------
extern "C" void kernel_launch(void* const* d_in, const int* in_sizes, int n_in,
                              void* d_out, int out_size) {
    const float* x      = (const float*)d_in[0];
    const float* scale1 = (const float*)d_in[1];
    const float* n1_w1  = (const float*)d_in[2];
    const float* n1_b1  = (const float*)d_in[3];
    const float* n1_w2  = (const float*)d_in[4];
    const float* n1_b2  = (const float*)d_in[5];
    const float* qkv_w  = (const float*)d_in[6];
    const float* qkv_b  = (const float*)d_in[7];
    const float* proj_w = (const float*)d_in[8];
    const float* proj_b = (const float*)d_in[9];
    const float* scale2 = (const float*)d_in[10];
    const float* n2_w1  = (const float*)d_in[11];
    const float* n2_b1  = (const float*)d_in[12];
    const float* n2_w2  = (const float*)d_in[13];
    const float* n2_b2  = (const float*)d_in[14];
    const float* mlp_w1 = (const float*)d_in[15];
    const float* mlp_b1 = (const float*)d_in[16];
    const float* mlp_w2 = (const float*)d_in[17];
    const float* mlp_b2 = (const float*)d_in[18];
    float* out = (float*)d_out;

    float *x2;
    __half* qkvh;
    __nv_bfloat16 *wb, *wsm, *wb2, *ws2, *xb, *xs, *obb, *obs, *x2b, *x2s, *mbb, *mbs;
    cudaGetSymbolAddress((void**)&qkvh, g_qkvh);
    cudaGetSymbolAddress((void**)&x2,  g_x2);
    cudaGetSymbolAddress((void**)&wb,  g_wb);
    cudaGetSymbolAddress((void**)&wsm, g_wsm);
    cudaGetSymbolAddress((void**)&wb2, g_wb2);
    cudaGetSymbolAddress((void**)&ws2, g_ws2);
    cudaGetSymbolAddress((void**)&xb,  g_xb);
    cudaGetSymbolAddress((void**)&xs,  g_xs);
    cudaGetSymbolAddress((void**)&obb, g_obb);
    cudaGetSymbolAddress((void**)&obs, g_obs);
    cudaGetSymbolAddress((void**)&x2b, g_x2b);
    cudaGetSymbolAddress((void**)&x2s, g_x2s);
    cudaGetSymbolAddress((void**)&mbb, g_mbb);
    cudaGetSymbolAddress((void**)&mbs, g_mbs);

    cudaFuncSetAttribute(attn_kernel, cudaFuncAttributeMaxDynamicSharedMemorySize, 65536);

    // ---- stage A ----
    colstats_kernel<<<192, 256>>>(x, xb, xs);                        // 1
    gamma1_kernel<<<24, 128>>>(n1_w1, n1_b1);                        // 2
    gamma2_kernel<<<12, 128>>>(n1_w2, n1_b2, scale1);                // 3 (zeroes g_sums)
    convwA_kernel<<<144, 256>>>(qkv_w, proj_w);                      // 4

    // qkv -> fp16 (pos,576), smem-staged coalesced transpose stores // 5
    gemm_kernel<192, 192, false, 0, false, 3, false, false><<<dim3(64, 9), 128>>>(
        wb, wsm, xb, xs, qkv_b, nullptr, (float*)qkvh, nullptr, nullptr, 576, NPOS);

    // attention (fp16 in) -> ob bf16 pairs (N,C)                    // 6
    attn_kernel<<<dim3(64, 6), 256, 65536>>>(qkvh, obb, obs);

    // proj + residual + stage-B stats -> x2 fp32 + bf16 pairs       // 7
    gemm_kernel<192, 192, true, 2, true, 0, true, true><<<dim3(64, 3), 128>>>(
        wb2, ws2, obb, obs, proj_b, x, x2, x2b, x2s, 192, NPOS);

    // ---- stage B ----
    gamma1_kernel<<<24, 128>>>(n2_w1, n2_b1);                        // 8
    gamma2_kernel<<<12, 128>>>(n2_w2, n2_b2, scale2);                // 9 (zeroes g_sums)
    convwB_kernel<<<1056, 256>>>(mlp_w1, mlp_w2, x2, mlp_b2, out);   // 10 (+ initout)

    // mlp1 + gelu -> mb bf16 pairs                                  // 11
    gemm_kernel<192, 192, false, 1, false, 0, true, false><<<dim3(64, 12), 128>>>(
        wb, wsm, x2b, x2s, mlp_b1, nullptr, nullptr, mbb, mbs, 768, NPOS);

    // mlp2 split-K x4 atomic-accumulate into pre-initialized out    // 12
    gemm_kernel<192, 768, false, 0, false, 2, false, false><<<dim3(64, 3, 4), 128>>>(
        wb2, ws2, mbb, mbs, mlp_b2, nullptr, out, nullptr, nullptr, 192, NPOS);
}

// round 13
// speedup vs baseline: 1.0809x; 1.0029x over previous
#include <cuda_runtime.h>
#include <cuda_fp16.h>
#include <cuda_bf16.h>
#include <math.h>

#define NPOS 4096
#define FULLM 0xffffffffu

// ---------------- scratch (static device globals; no allocation) -------------
__device__ __half g_qkvh[NPOS * 576];          // (pos, 576) pos-major fp16
__device__ float g_sums[2 * 192];              // per-channel sum / sumsq
__device__ float g_mult[192];                  // scale*gamma/rms
__device__ float g_h[384];                     // norm-MLP hidden
// bf16 big/small pairs
__device__ __nv_bfloat16 g_wb [768 * 192],  g_wsm[768 * 192];    // W bank 0 (qkv, then mlp_w1)
__device__ __nv_bfloat16 g_wb2[192 * 768],  g_ws2[192 * 768];    // W bank 1 (proj, then mlp_w2)
__device__ __nv_bfloat16 g_xb [192 * NPOS], g_xs [192 * NPOS];   // x pairs (C,N)
__device__ __nv_bfloat16 g_obb[NPOS * 192], g_obs[NPOS * 192];   // attn out pairs (N,C)
__device__ __nv_bfloat16 g_x2b[192 * NPOS], g_x2s[192 * NPOS];   // x2 pairs (C,N)
__device__ __nv_bfloat16 g_mbb[768 * NPOS], g_mbs[768 * NPOS];   // mlp hidden pairs (C,N)

// ---------------- helpers -----------------------------------------------------
__device__ __forceinline__ unsigned smem_u32(const void* p) {
    return (unsigned)__cvta_generic_to_shared(p);
}
__device__ __forceinline__ void cp16(unsigned dst, const void* src) {
    asm volatile("cp.async.cg.shared.global [%0], [%1], 16;" :: "r"(dst), "l"(src));
}
__device__ __forceinline__ void cp_commit() { asm volatile("cp.async.commit_group;"); }
template <int W> __device__ __forceinline__ void cp_wait() {
    asm volatile("cp.async.wait_group %0;" :: "n"(W));
}
__device__ __forceinline__ void mma_bf16(float* d, const unsigned* a, const unsigned* b) {
    asm volatile(
        "mma.sync.aligned.m16n8k16.row.col.f32.bf16.bf16.f32 "
        "{%0,%1,%2,%3},{%4,%5,%6,%7},{%8,%9},{%0,%1,%2,%3};"
        : "+f"(d[0]), "+f"(d[1]), "+f"(d[2]), "+f"(d[3])
        : "r"(a[0]), "r"(a[1]), "r"(a[2]), "r"(a[3]), "r"(b[0]), "r"(b[1]));
}
__device__ __forceinline__ void ldsm_x2_trans(unsigned& r0, unsigned& r1, unsigned addr) {
    asm volatile("ldmatrix.sync.aligned.m8n8.x2.trans.shared.b16 {%0,%1}, [%2];"
                 : "=r"(r0), "=r"(r1) : "r"(addr));
}
__device__ __forceinline__ void store_pair(__nv_bfloat16* pb, __nv_bfloat16* ps,
                                           size_t idx, float v0, float v1) {
    __nv_bfloat16 b0 = __float2bfloat16_rn(v0), b1 = __float2bfloat16_rn(v1);
    __nv_bfloat16 s0 = __float2bfloat16_rn(v0 - __bfloat162float(b0));
    __nv_bfloat16 s1 = __float2bfloat16_rn(v1 - __bfloat162float(b1));
    *(__nv_bfloat162*)(pb + idx) = __halves2bfloat162(b0, b1);
    *(__nv_bfloat162*)(ps + idx) = __halves2bfloat162(s0, s1);
}
__device__ __forceinline__ void split4(float4 v, __nv_bfloat16* db, __nv_bfloat16* ds, int idx) {
    __nv_bfloat16 b0 = __float2bfloat16_rn(v.x), b1 = __float2bfloat16_rn(v.y);
    __nv_bfloat16 b2 = __float2bfloat16_rn(v.z), b3 = __float2bfloat16_rn(v.w);
    *(__nv_bfloat162*)(db + idx)     = __halves2bfloat162(b0, b1);
    *(__nv_bfloat162*)(db + idx + 2) = __halves2bfloat162(b2, b3);
    *(__nv_bfloat162*)(ds + idx) = __halves2bfloat162(
        __float2bfloat16_rn(v.x - __bfloat162float(b0)),
        __float2bfloat16_rn(v.y - __bfloat162float(b1)));
    *(__nv_bfloat162*)(ds + idx + 2) = __halves2bfloat162(
        __float2bfloat16_rn(v.z - __bfloat162float(b2)),
        __float2bfloat16_rn(v.w - __bfloat162float(b3)));
}

// ---------------- per-channel stats over x + bf16 pair conversion -------------
__global__ void colstats_kernel(const float* __restrict__ x,
                                __nv_bfloat16* __restrict__ xb,
                                __nv_bfloat16* __restrict__ xs) {
    int c = blockIdx.x;
    const float* p = x + c * NPOS;
    float s = 0.f, s2 = 0.f;
    for (int i = threadIdx.x; i < NPOS; i += 256) {
        float v = p[i];
        s += v;
        s2 = fmaf(v, v, s2);
        __nv_bfloat16 b = __float2bfloat16_rn(v);
        xb[c * NPOS + i] = b;
        xs[c * NPOS + i] = __float2bfloat16_rn(v - __bfloat162float(b));
    }
    __shared__ float sh0[256], sh1[256];
    sh0[threadIdx.x] = s; sh1[threadIdx.x] = s2;
    __syncthreads();
    for (int o = 128; o > 0; o >>= 1) {
        if (threadIdx.x < o) {
            sh0[threadIdx.x] += sh0[threadIdx.x + o];
            sh1[threadIdx.x] += sh1[threadIdx.x + o];
        }
        __syncthreads();
    }
    if (threadIdx.x == 0) {
        g_sums[c]       = sh0[0];
        g_sums[192 + c] = sh1[0];
    }
}

// ---------------- norm-MLP layer 1 --------------------------------------------
__global__ void gamma1_kernel(const float* __restrict__ w1, const float* __restrict__ b1) {
    const int warp = threadIdx.x >> 5, lane = threadIdx.x & 31;
    const int ob = blockIdx.x * 16 + warp * 4;
    float a0 = 0.f, a1 = 0.f, a2 = 0.f, a3 = 0.f;
    #pragma unroll
    for (int j = 0; j < 6; j++) {
        float sv = g_sums[lane + j * 32] * (1.0f / 4096.0f);
        a0 = fmaf(sv, w1[(ob + 0) * 192 + lane + j * 32], a0);
        a1 = fmaf(sv, w1[(ob + 1) * 192 + lane + j * 32], a1);
        a2 = fmaf(sv, w1[(ob + 2) * 192 + lane + j * 32], a2);
        a3 = fmaf(sv, w1[(ob + 3) * 192 + lane + j * 32], a3);
    }
    #pragma unroll
    for (int off = 16; off; off >>= 1) {
        a0 += __shfl_xor_sync(FULLM, a0, off);
        a1 += __shfl_xor_sync(FULLM, a1, off);
        a2 += __shfl_xor_sync(FULLM, a2, off);
        a3 += __shfl_xor_sync(FULLM, a3, off);
    }
    if (lane == 0) {
        g_h[ob + 0] = fmaxf(a0 + b1[ob + 0], 0.f);
        g_h[ob + 1] = fmaxf(a1 + b1[ob + 1], 0.f);
        g_h[ob + 2] = fmaxf(a2 + b1[ob + 2], 0.f);
        g_h[ob + 3] = fmaxf(a3 + b1[ob + 3], 0.f);
    }
}

// ---------------- norm-MLP layer 2 -> g_mult; zeroes g_sums -------------------
__global__ void gamma2_kernel(const float* __restrict__ w2, const float* __restrict__ b2,
                              const float* __restrict__ scale) {
    const int warp = threadIdx.x >> 5, lane = threadIdx.x & 31;
    const int ob = blockIdx.x * 16 + warp * 4;
    float a0 = 0.f, a1 = 0.f, a2 = 0.f, a3 = 0.f;
    #pragma unroll
    for (int j = 0; j < 12; j++) {
        float hv = g_h[lane + j * 32];
        a0 = fmaf(hv, w2[(ob + 0) * 384 + lane + j * 32], a0);
        a1 = fmaf(hv, w2[(ob + 1) * 384 + lane + j * 32], a1);
        a2 = fmaf(hv, w2[(ob + 2) * 384 + lane + j * 32], a2);
        a3 = fmaf(hv, w2[(ob + 3) * 384 + lane + j * 32], a3);
    }
    #pragma unroll
    for (int off = 16; off; off >>= 1) {
        a0 += __shfl_xor_sync(FULLM, a0, off);
        a1 += __shfl_xor_sync(FULLM, a1, off);
        a2 += __shfl_xor_sync(FULLM, a2, off);
        a3 += __shfl_xor_sync(FULLM, a3, off);
    }
    if (lane == 0) {
        #pragma unroll
        for (int u = 0; u < 4; u++) {
            float a = (u == 0 ? a0 : u == 1 ? a1 : u == 2 ? a2 : a3) + b2[ob + u];
            float gamma = 1.f / (1.f + expf(-a));
            float rms = sqrtf(g_sums[192 + ob + u] * (1.0f / 4096.0f) + 1e-6f);
            g_mult[ob + u] = scale[ob + u] * gamma / rms;
            g_sums[ob + u] = 0.f;
            g_sums[192 + ob + u] = 0.f;
        }
    }
}

// ---------------- convwA: split qkv_w (x g_mult) + proj_w, ILP x2 -------------
// 72 blocks x 256 thr; each thread 2 independent float4s (stride 18432).
__global__ void convwA_kernel(const float* __restrict__ qkvw, const float* __restrict__ projw) {
    int base = blockIdx.x * 256 + threadIdx.x;       // 0..18431
    float4 v[2];
    #pragma unroll
    for (int s = 0; s < 2; s++) {
        int i4 = base + s * 18432;
        v[s] = (i4 < 27648) ? ((const float4*)qkvw)[i4]
                            : ((const float4*)projw)[i4 - 27648];
    }
    #pragma unroll
    for (int s = 0; s < 2; s++) {
        int i4 = base + s * 18432;
        if (i4 < 27648) {                    // qkv_w: fold g_mult
            int idx = i4 * 4;
            float4 t = v[s];
            int m = idx % 192;
            t.x *= g_mult[m]; t.y *= g_mult[m + 1]; t.z *= g_mult[m + 2]; t.w *= g_mult[m + 3];
            split4(t, g_wb, g_wsm, idx);
        } else {                             // proj_w
            int j = i4 - 27648;
            split4(v[s], g_wb2, g_ws2, j * 4);
        }
    }
}

// ---------------- convwB: mlp_w1 (x g_mult) + mlp_w2 splits + initout, ILP x2 --
// 528 blocks x 256 thr; each thread 2 independent float4 items (stride 135168).
// initout reconstructs: out = (x2b + x2s) + bias  (from proj's bf16 pairs).
__global__ void convwB_kernel(const float* __restrict__ w1, const float* __restrict__ w2m,
                              const __nv_bfloat16* __restrict__ x2b,
                              const __nv_bfloat16* __restrict__ x2s,
                              const float* __restrict__ bias, float* __restrict__ out) {
    int base = blockIdx.x * 256 + threadIdx.x;       // 0..135167
    #pragma unroll
    for (int s = 0; s < 2; s++) {
        int i4 = base + s * 135168;
        if (i4 < 36864) {                    // mlp_w1: fold g_mult
            int idx = i4 * 4;
            float4 v = ((const float4*)w1)[i4];
            int m = idx % 192;
            v.x *= g_mult[m]; v.y *= g_mult[m + 1]; v.z *= g_mult[m + 2]; v.w *= g_mult[m + 3];
            split4(v, g_wb, g_wsm, idx);
        } else if (i4 < 73728) {             // mlp_w2
            int j = i4 - 36864;
            split4(((const float4*)w2m)[j], g_wb2, g_ws2, j * 4);
        } else {                             // initout (196608 float4s)
            int j = i4 - 73728;
            float b = bias[j >> 10];
            uint2 pb = *(const uint2*)(x2b + j * 4);
            uint2 psm = *(const uint2*)(x2s + j * 4);
            float2 b0 = __bfloat1622float2(*(__nv_bfloat162*)&pb.x);
            float2 b1 = __bfloat1622float2(*(__nv_bfloat162*)&pb.y);
            float2 s0 = __bfloat1622float2(*(__nv_bfloat162*)&psm.x);
            float2 s1 = __bfloat1622float2(*(__nv_bfloat162*)&psm.y);
            float4 v = make_float4(b0.x + s0.x + b, b0.y + s0.y + b,
                                   b1.x + s1.x + b, b1.y + s1.y + b);
            ((float4*)out)[j] = v;
        }
    }
}

// ---------------- GEMM v9: bf16x3 pairs, cp.async 3-stage ---------------------
// OUTM: 0 none/pairs-only, 2 atomicAdd (Co,N), 3 fp16 (N,Co) smem-staged.
template <int CI, int CIFULL, bool BNMAJ, int EPI, bool STATS, int OUTM, bool PAIRS, bool WF32>
__global__ void __launch_bounds__(128)
gemm_kernel(const __nv_bfloat16* __restrict__ Awb, const __nv_bfloat16* __restrict__ Aws,
            const __nv_bfloat16* __restrict__ Bxb, const __nv_bfloat16* __restrict__ Bxs,
            const float* __restrict__ bias, const float* __restrict__ res,
            float* __restrict__ out, __nv_bfloat16* __restrict__ pb,
            __nv_bfloat16* __restrict__ ps, int Co, int N) {
    constexpr int NK = CI / 16;
    constexpr int BW = BNMAJ ? (64 * 12) : (16 * 36);
    __shared__ uint sA[3][2][64 * 12];
    __shared__ uint sB[3][2][BW];
    __shared__ __half sT[(OUTM == 3) ? 64 * 72 : 8];

    const int bn = blockIdx.x * 64;
    const int bm = blockIdx.y * 64;
    const int kbase = blockIdx.z * CI;
    const int tid = threadIdx.x;
    const int warp = tid >> 5, lane = tid & 31;
    const int gid = lane >> 2, tig = lane & 3;
    const int wmb = (warp >> 1) * 32;
    const int wnb = (warp & 1) * 32;

    auto stage = [&](int t, int st) {
        const int kk = kbase + t * 16;
        {
            int row = tid >> 1, ch = tid & 1;
            size_t go = (size_t)(bm + row) * CIFULL + kk + ch * 8;
            cp16(smem_u32(&sA[st][0][row * 12 + ch * 4]), Awb + go);
            cp16(smem_u32(&sA[st][1][row * 12 + ch * 4]), Aws + go);
        }
        if (BNMAJ) {
            int row = tid >> 1, ch = tid & 1;
            size_t go = (size_t)(bn + row) * CIFULL + kk + ch * 8;
            cp16(smem_u32(&sB[st][0][row * 12 + ch * 4]), Bxb + go);
            cp16(smem_u32(&sB[st][1][row * 12 + ch * 4]), Bxs + go);
        } else {
            int row = tid >> 3, ch = tid & 7;
            size_t go = (size_t)(kk + row) * N + bn + ch * 8;
            cp16(smem_u32((char*)&sB[st][0][0] + row * 144 + ch * 16), Bxb + go);
            cp16(smem_u32((char*)&sB[st][1][0] + row * 144 + ch * 16), Bxs + go);
        }
        cp_commit();
    };

    float d[2][4][4];
    #pragma unroll
    for (int mt = 0; mt < 2; mt++)
        #pragma unroll
        for (int j = 0; j < 4; j++)
            #pragma unroll
            for (int e = 0; e < 4; e++) d[mt][j][e] = 0.f;

    stage(0, 0);
    stage(1, 1);

    #pragma unroll 1
    for (int t = 0; t < NK; t++) {
        const int st = t % 3;
        if (t == NK - 1) cp_wait<0>(); else cp_wait<1>();
        __syncthreads();

        unsigned Ab[2][4], As[2][4];
        #pragma unroll
        for (int mt = 0; mt < 2; mt++) {
            int m0 = wmb + 16 * mt + gid;
            Ab[mt][0] = sA[st][0][m0 * 12 + tig];
            Ab[mt][1] = sA[st][0][(m0 + 8) * 12 + tig];
            Ab[mt][2] = sA[st][0][m0 * 12 + tig + 4];
            Ab[mt][3] = sA[st][0][(m0 + 8) * 12 + tig + 4];
            As[mt][0] = sA[st][1][m0 * 12 + tig];
            As[mt][1] = sA[st][1][(m0 + 8) * 12 + tig];
            As[mt][2] = sA[st][1][m0 * 12 + tig + 4];
            As[mt][3] = sA[st][1][(m0 + 8) * 12 + tig + 4];
        }
        #pragma unroll
        for (int j = 0; j < 4; j++) {
            unsigned Bb[2], Bs[2];
            if (BNMAJ) {
                int n0 = wnb + 8 * j + gid;
                Bb[0] = sB[st][0][n0 * 12 + tig];
                Bb[1] = sB[st][0][n0 * 12 + tig + 4];
                Bs[0] = sB[st][1][n0 * 12 + tig];
                Bs[1] = sB[st][1][n0 * 12 + tig + 4];
            } else {
                int boff = ((lane & 15) * 72 + wnb + 8 * j) * 2;
                ldsm_x2_trans(Bb[0], Bb[1], smem_u32((char*)&sB[st][0][0] + boff));
                ldsm_x2_trans(Bs[0], Bs[1], smem_u32((char*)&sB[st][1][0] + boff));
            }
            #pragma unroll
            for (int mt = 0; mt < 2; mt++) {
                mma_bf16(d[mt][j], Ab[mt], Bb);
                mma_bf16(d[mt][j], As[mt], Bb);
                mma_bf16(d[mt][j], Ab[mt], Bs);
            }
        }
        if (t + 2 < NK) stage(t + 2, (t + 2) % 3);
    }

    // ---- epilogue ----
    const int gn0 = bn + wnb + 2 * tig;
    #pragma unroll
    for (int mt = 0; mt < 2; mt++) {
        #pragma unroll
        for (int half = 0; half < 2; half++) {
            int m = bm + wmb + 16 * mt + gid + 8 * half;
            float bv = (OUTM == 2) ? 0.f : bias[m];
            float v[8];
            #pragma unroll
            for (int j = 0; j < 4; j++) {
                v[2 * j]     = d[mt][j][2 * half]     + bv;
                v[2 * j + 1] = d[mt][j][2 * half + 1] + bv;
            }
            if (EPI == 1) {
                #pragma unroll
                for (int e = 0; e < 8; e++) {
                    float u = v[e];
                    v[e] = u * 0.5f * (1.f + erff(u * 0.70710678118654752f));
                }
            }
            if (EPI == 2) {
                #pragma unroll
                for (int j = 0; j < 4; j++) {
                    float2 r2 = *(const float2*)&res[(size_t)m * N + gn0 + 8 * j];
                    v[2 * j] += r2.x; v[2 * j + 1] += r2.y;
                }
            }
            if (STATS) {
                float ls = 0.f, ls2 = 0.f;
                #pragma unroll
                for (int e = 0; e < 8; e++) { ls += v[e]; ls2 = fmaf(v[e], v[e], ls2); }
                ls  += __shfl_xor_sync(FULLM, ls, 1);  ls  += __shfl_xor_sync(FULLM, ls, 2);
                ls2 += __shfl_xor_sync(FULLM, ls2, 1); ls2 += __shfl_xor_sync(FULLM, ls2, 2);
                if (tig == 0) {
                    atomicAdd(&g_sums[m], ls);
                    atomicAdd(&g_sums[192 + m], ls2);
                }
            }
            if (PAIRS) {
                #pragma unroll
                for (int j = 0; j < 4; j++)
                    store_pair(pb, ps, (size_t)m * N + gn0 + 8 * j, v[2 * j], v[2 * j + 1]);
            }
            if (OUTM == 3) {
                int ml = wmb + 16 * mt + gid + 8 * half;
                #pragma unroll
                for (int j = 0; j < 4; j++) {
                    int nl = wnb + 2 * tig + 8 * j;
                    sT[nl * 72 + ml]       = __float2half(v[2 * j]);
                    sT[(nl + 1) * 72 + ml] = __float2half(v[2 * j + 1]);
                }
            } else if (OUTM == 2) {
                #pragma unroll
                for (int j = 0; j < 4; j++) {
                    atomicAdd(&out[(size_t)m * N + gn0 + 8 * j],     v[2 * j]);
                    atomicAdd(&out[(size_t)m * N + gn0 + 8 * j + 1], v[2 * j + 1]);
                }
            } else if (WF32) {
                #pragma unroll
                for (int j = 0; j < 4; j++)
                    *(float2*)&out[(size_t)m * N + gn0 + 8 * j] = make_float2(v[2 * j], v[2 * j + 1]);
            }
        }
    }
    if (OUTM == 3) {
        __syncthreads();
        __half* oh = (__half*)out;
        #pragma unroll
        for (int i = 0; i < 4; i++) {
            int idx = tid + i * 128;
            int row = idx >> 3, ch = idx & 7;
            *(uint4*)(oh + (size_t)(bn + row) * Co + bm + ch * 8) =
                *(const uint4*)(sT + row * 72 + ch * 8);
        }
    }
}

// ---------------- 3D neighborhood attention (fp16 qkv input) ------------------
__global__ void __launch_bounds__(256) attn_kernel(const __half* __restrict__ qkvh,
                                                   __nv_bfloat16* __restrict__ obb,
                                                   __nv_bfloat16* __restrict__ obs) {
    extern __shared__ __align__(16) half2 sKV[];   // sK[8192] then sV[8192]
    half2* sK = sKV;
    half2* sV = sKV + 8192;

    const int tile = blockIdx.x, head = blockIdx.y;
    const int tid = threadIdx.x;

    const int Td = ((tile >> 4) & 3) * 4, Th = ((tile >> 2) & 3) * 4, Tw = (tile & 3) * 4;
    const int Bd = min(max(Td - 2, 0), 8);
    const int Bh = min(max(Th - 2, 0), 8);
    const int Bw = min(max(Tw - 2, 0), 8);

    #pragma unroll
    for (int it = 0; it < 16; it++) {
        int i = tid + it * 256;
        int row = i >> 3, g = i & 7;
        int rd = row >> 6, rh = (row >> 3) & 7, rw = row & 7;
        int gpos = ((Bd + rd) << 8) + ((Bh + rh) << 4) + (Bw + rw);
        int mat = g >> 2, c = g & 3;
        const __half* src = qkvh + (size_t)gpos * 576 + 192 + 192 * mat + head * 32 + c * 8;
        half2* dst = (mat ? sV : sK) + row * 16 + c * 4;
        *(uint4*)dst = *(const uint4*)src;
    }

    const int quarter = tid & 3, vox = tid >> 2;
    const int aw = vox & 3, ah = (vox >> 2) & 3, ad = vox >> 4;
    const int vd = Td + ad, vh = Th + ah, vw = Tw + aw;
    const int gv = (vd << 8) + (vh << 4) + vw;
    const int ld = min(max(vd - 2, 0), 11) - Bd;
    const int lh = min(max(vh - 2, 0), 11) - Bh;
    const int lw = min(max(vw - 2, 0), 11) - Bw;
    const int rbase = ld * 64 + lh * 8 + lw;
    const int lane = tid & 31;

    float q[8];
    {
        const __half* qp = qkvh + (size_t)gv * 576 + head * 32 + quarter * 8;
        uint4 qq = *(const uint4*)qp;
        const half2* qh = (const half2*)&qq;
        #pragma unroll
        for (int c = 0; c < 4; c++) {
            float2 f = __half22float2(qh[c]);
            q[2 * c]     = f.x * 0.17677669529663687f;
            q[2 * c + 1] = f.y * 0.17677669529663687f;
        }
    }
    __syncthreads();

    float sc[32];
    #pragma unroll
    for (int i = 0; i < 32; i++) sc[i] = -1e30f;

    #pragma unroll
    for (int j = 0; j < 125; j++) {
        const int a = j / 25, b = (j / 5) % 5, c5 = j % 5;
        int row = rbase + a * 64 + b * 8 + c5;
        uint4 kk = *(const uint4*)(sK + row * 16 + quarter * 4);
        float2 f0 = __half22float2(*reinterpret_cast<half2*>(&kk.x));
        float2 f1 = __half22float2(*reinterpret_cast<half2*>(&kk.y));
        float2 f2 = __half22float2(*reinterpret_cast<half2*>(&kk.z));
        float2 f3 = __half22float2(*reinterpret_cast<half2*>(&kk.w));
        float p = q[0] * f0.x;
        p = fmaf(q[1], f0.y, p); p = fmaf(q[2], f1.x, p); p = fmaf(q[3], f1.y, p);
        p = fmaf(q[4], f2.x, p); p = fmaf(q[5], f2.y, p);
        p = fmaf(q[6], f3.x, p); p = fmaf(q[7], f3.y, p);
        p += __shfl_xor_sync(FULLM, p, 1);
        p += __shfl_xor_sync(FULLM, p, 2);
        if ((j & 3) == quarter) sc[j >> 2] = p;
    }

    float mx = -1e30f;
    #pragma unroll
    for (int i = 0; i < 32; i++) mx = fmaxf(mx, sc[i]);
    mx = fmaxf(mx, __shfl_xor_sync(FULLM, mx, 1));
    mx = fmaxf(mx, __shfl_xor_sync(FULLM, mx, 2));
    float tot = 0.f;
    #pragma unroll
    for (int i = 0; i < 32; i++) { sc[i] = __expf(sc[i] - mx); tot += sc[i]; }
    tot += __shfl_xor_sync(FULLM, tot, 1);
    tot += __shfl_xor_sync(FULLM, tot, 2);
    float inv = 1.f / tot;

    float o8[8] = {0.f, 0.f, 0.f, 0.f, 0.f, 0.f, 0.f, 0.f};
    #pragma unroll
    for (int j = 0; j < 125; j++) {
        const int a = j / 25, b = (j / 5) % 5, c5 = j % 5;
        float p = __shfl_sync(FULLM, sc[j >> 2], (lane & ~3) | (j & 3));
        int row = rbase + a * 64 + b * 8 + c5;
        uint4 vvp = *(const uint4*)(sV + row * 16 + quarter * 4);
        float2 f0 = __half22float2(*reinterpret_cast<half2*>(&vvp.x));
        float2 f1 = __half22float2(*reinterpret_cast<half2*>(&vvp.y));
        float2 f2 = __half22float2(*reinterpret_cast<half2*>(&vvp.z));
        float2 f3 = __half22float2(*reinterpret_cast<half2*>(&vvp.w));
        o8[0] = fmaf(p, f0.x, o8[0]); o8[1] = fmaf(p, f0.y, o8[1]);
        o8[2] = fmaf(p, f1.x, o8[2]); o8[3] = fmaf(p, f1.y, o8[3]);
        o8[4] = fmaf(p, f2.x, o8[4]); o8[5] = fmaf(p, f2.y, o8[5]);
        o8[6] = fmaf(p, f3.x, o8[6]); o8[7] = fmaf(p, f3.y, o8[7]);
    }
    size_t ob0 = (size_t)gv * 192 + head * 32 + quarter * 8;
    #pragma unroll
    for (int c = 0; c < 4; c++)
        store_pair(obb, obs, ob0 + 2 * c, o8[2 * c] * inv, o8[2 * c + 1] * inv);
}

// ---------------- orchestration ----------------------------------------------
extern "C" void kernel_launch(void* const* d_in, const int* in_sizes, int n_in,
                              void* d_out, int out_size) {
    const float* x      = (const float*)d_in[0];
    const float* scale1 = (const float*)d_in[1];
    const float* n1_w1  = (const float*)d_in[2];
    const float* n1_b1  = (const float*)d_in[3];
    const float* n1_w2  = (const float*)d_in[4];
    const float* n1_b2  = (const float*)d_in[5];
    const float* qkv_w  = (const float*)d_in[6];
    const float* qkv_b  = (const float*)d_in[7];
    const float* proj_w = (const float*)d_in[8];
    const float* proj_b = (const float*)d_in[9];
    const float* scale2 = (const float*)d_in[10];
    const float* n2_w1  = (const float*)d_in[11];
    const float* n2_b1  = (const float*)d_in[12];
    const float* n2_w2  = (const float*)d_in[13];
    const float* n2_b2  = (const float*)d_in[14];
    const float* mlp_w1 = (const float*)d_in[15];
    const float* mlp_b1 = (const float*)d_in[16];
    const float* mlp_w2 = (const float*)d_in[17];
    const float* mlp_b2 = (const float*)d_in[18];
    float* out = (float*)d_out;

    __half* qkvh;
    __nv_bfloat16 *wb, *wsm, *wb2, *ws2, *xb, *xs, *obb, *obs, *x2b, *x2s, *mbb, *mbs;
    cudaGetSymbolAddress((void**)&qkvh, g_qkvh);
    cudaGetSymbolAddress((void**)&wb,  g_wb);
    cudaGetSymbolAddress((void**)&wsm, g_wsm);
    cudaGetSymbolAddress((void**)&wb2, g_wb2);
    cudaGetSymbolAddress((void**)&ws2, g_ws2);
    cudaGetSymbolAddress((void**)&xb,  g_xb);
    cudaGetSymbolAddress((void**)&xs,  g_xs);
    cudaGetSymbolAddress((void**)&obb, g_obb);
    cudaGetSymbolAddress((void**)&obs, g_obs);
    cudaGetSymbolAddress((void**)&x2b, g_x2b);
    cudaGetSymbolAddress((void**)&x2s, g_x2s);
    cudaGetSymbolAddress((void**)&mbb, g_mbb);
    cudaGetSymbolAddress((void**)&mbs, g_mbs);

    cudaFuncSetAttribute(attn_kernel, cudaFuncAttributeMaxDynamicSharedMemorySize, 65536);

    // ---- stage A ----
    colstats_kernel<<<192, 256>>>(x, xb, xs);                        // 1
    gamma1_kernel<<<24, 128>>>(n1_w1, n1_b1);                        // 2
    gamma2_kernel<<<12, 128>>>(n1_w2, n1_b2, scale1);                // 3 (zeroes g_sums)
    convwA_kernel<<<72, 256>>>(qkv_w, proj_w);                       // 4

    // qkv -> fp16 (pos,576), smem-staged coalesced transpose stores // 5
    gemm_kernel<192, 192, false, 0, false, 3, false, false><<<dim3(64, 9), 128>>>(
        wb, wsm, xb, xs, qkv_b, nullptr, (float*)qkvh, nullptr, nullptr, 576, NPOS);

    // attention (fp16 in) -> ob bf16 pairs (N,C)                    // 6
    attn_kernel<<<dim3(64, 6), 256, 65536>>>(qkvh, obb, obs);

    // proj + residual + stage-B stats -> x2 bf16 pairs only         // 7
    gemm_kernel<192, 192, true, 2, true, 0, true, false><<<dim3(64, 3), 128>>>(
        wb2, ws2, obb, obs, proj_b, x, nullptr, x2b, x2s, 192, NPOS);

    // ---- stage B ----
    gamma1_kernel<<<24, 128>>>(n2_w1, n2_b1);                        // 8
    gamma2_kernel<<<12, 128>>>(n2_w2, n2_b2, scale2);                // 9 (zeroes g_sums)
    convwB_kernel<<<528, 256>>>(mlp_w1, mlp_w2, x2b, x2s, mlp_b2, out);  // 10 (+ initout)

    // mlp1 + gelu -> mb bf16 pairs                                  // 11
    gemm_kernel<192, 192, false, 1, false, 0, true, false><<<dim3(64, 12), 128>>>(
        wb, wsm, x2b, x2s, mlp_b1, nullptr, nullptr, mbb, mbs, 768, NPOS);

    // mlp2 split-K x4 atomic-accumulate into pre-initialized out    // 12
    gemm_kernel<192, 768, false, 0, false, 2, false, false><<<dim3(64, 3, 4), 128>>>(
        wb2, ws2, mbb, mbs, mlp_b2, nullptr, out, nullptr, nullptr, 192, NPOS);
}

// round 14
// speedup vs baseline: 1.0981x; 1.0159x over previous
#include <cuda_runtime.h>
#include <cuda_fp16.h>
#include <cuda_bf16.h>
#include <math.h>

#define NPOS 4096
#define FULLM 0xffffffffu

// ---------------- scratch (static device globals; no allocation) -------------
__device__ __half g_qkvh[NPOS * 576];          // (pos, 576) pos-major fp16
__device__ float g_sums[2 * 192];              // per-channel sum / sumsq
__device__ float g_mult[192];                  // scale*gamma/rms
__device__ float g_h[384];                     // norm-MLP hidden
// bf16 big/small pairs
__device__ __nv_bfloat16 g_wb [768 * 192],  g_wsm[768 * 192];    // W bank 0 (qkv, then mlp_w1)
__device__ __nv_bfloat16 g_wb2[192 * 768],  g_ws2[192 * 768];    // W bank 1 (proj, then mlp_w2)
__device__ __nv_bfloat16 g_w3b[192 * 768],  g_w3s[192 * 768];    // W bank 2 (mlp_w2)
__device__ __nv_bfloat16 g_xb [192 * NPOS], g_xs [192 * NPOS];   // x pairs (C,N)
__device__ __nv_bfloat16 g_obb[NPOS * 192], g_obs[NPOS * 192];   // attn out pairs (N,C)
__device__ __nv_bfloat16 g_x2b[192 * NPOS], g_x2s[192 * NPOS];   // x2 pairs (C,N)
__device__ __nv_bfloat16 g_mbb[768 * NPOS], g_mbs[768 * NPOS];   // mlp hidden pairs (C,N)

// ---------------- helpers -----------------------------------------------------
__device__ __forceinline__ unsigned smem_u32(const void* p) {
    return (unsigned)__cvta_generic_to_shared(p);
}
__device__ __forceinline__ void cp16(unsigned dst, const void* src) {
    asm volatile("cp.async.cg.shared.global [%0], [%1], 16;" :: "r"(dst), "l"(src));
}
__device__ __forceinline__ void cp_commit() { asm volatile("cp.async.commit_group;"); }
template <int W> __device__ __forceinline__ void cp_wait() {
    asm volatile("cp.async.wait_group %0;" :: "n"(W));
}
__device__ __forceinline__ void mma_bf16(float* d, const unsigned* a, const unsigned* b) {
    asm volatile(
        "mma.sync.aligned.m16n8k16.row.col.f32.bf16.bf16.f32 "
        "{%0,%1,%2,%3},{%4,%5,%6,%7},{%8,%9},{%0,%1,%2,%3};"
        : "+f"(d[0]), "+f"(d[1]), "+f"(d[2]), "+f"(d[3])
        : "r"(a[0]), "r"(a[1]), "r"(a[2]), "r"(a[3]), "r"(b[0]), "r"(b[1]));
}
__device__ __forceinline__ void ldsm_x2_trans(unsigned& r0, unsigned& r1, unsigned addr) {
    asm volatile("ldmatrix.sync.aligned.m8n8.x2.trans.shared.b16 {%0,%1}, [%2];"
                 : "=r"(r0), "=r"(r1) : "r"(addr));
}
__device__ __forceinline__ void store_pair(__nv_bfloat16* pb, __nv_bfloat16* ps,
                                           size_t idx, float v0, float v1) {
    __nv_bfloat16 b0 = __float2bfloat16_rn(v0), b1 = __float2bfloat16_rn(v1);
    __nv_bfloat16 s0 = __float2bfloat16_rn(v0 - __bfloat162float(b0));
    __nv_bfloat16 s1 = __float2bfloat16_rn(v1 - __bfloat162float(b1));
    *(__nv_bfloat162*)(pb + idx) = __halves2bfloat162(b0, b1);
    *(__nv_bfloat162*)(ps + idx) = __halves2bfloat162(s0, s1);
}
__device__ __forceinline__ void split4(float4 v, __nv_bfloat16* db, __nv_bfloat16* ds, int idx) {
    __nv_bfloat16 b0 = __float2bfloat16_rn(v.x), b1 = __float2bfloat16_rn(v.y);
    __nv_bfloat16 b2 = __float2bfloat16_rn(v.z), b3 = __float2bfloat16_rn(v.w);
    *(__nv_bfloat162*)(db + idx)     = __halves2bfloat162(b0, b1);
    *(__nv_bfloat162*)(db + idx + 2) = __halves2bfloat162(b2, b3);
    *(__nv_bfloat162*)(ds + idx) = __halves2bfloat162(
        __float2bfloat16_rn(v.x - __bfloat162float(b0)),
        __float2bfloat16_rn(v.y - __bfloat162float(b1)));
    *(__nv_bfloat162*)(ds + idx + 2) = __halves2bfloat162(
        __float2bfloat16_rn(v.z - __bfloat162float(b2)),
        __float2bfloat16_rn(v.w - __bfloat162float(b3)));
}

// ---------------- per-channel stats over x + bf16 pair conversion -------------
__global__ void colstats_kernel(const float* __restrict__ x,
                                __nv_bfloat16* __restrict__ xb,
                                __nv_bfloat16* __restrict__ xs) {
    int c = blockIdx.x;
    const float* p = x + c * NPOS;
    float s = 0.f, s2 = 0.f;
    for (int i = threadIdx.x; i < NPOS; i += 256) {
        float v = p[i];
        s += v;
        s2 = fmaf(v, v, s2);
        __nv_bfloat16 b = __float2bfloat16_rn(v);
        xb[c * NPOS + i] = b;
        xs[c * NPOS + i] = __float2bfloat16_rn(v - __bfloat162float(b));
    }
    __shared__ float sh0[256], sh1[256];
    sh0[threadIdx.x] = s; sh1[threadIdx.x] = s2;
    __syncthreads();
    for (int o = 128; o > 0; o >>= 1) {
        if (threadIdx.x < o) {
            sh0[threadIdx.x] += sh0[threadIdx.x + o];
            sh1[threadIdx.x] += sh1[threadIdx.x + o];
        }
        __syncthreads();
    }
    if (threadIdx.x == 0) {
        g_sums[c]       = sh0[0];
        g_sums[192 + c] = sh1[0];
    }
}

// ---------------- norm-MLP layer 1 --------------------------------------------
__global__ void gamma1_kernel(const float* __restrict__ w1, const float* __restrict__ b1) {
    const int warp = threadIdx.x >> 5, lane = threadIdx.x & 31;
    const int ob = blockIdx.x * 16 + warp * 4;
    float a0 = 0.f, a1 = 0.f, a2 = 0.f, a3 = 0.f;
    #pragma unroll
    for (int j = 0; j < 6; j++) {
        float sv = g_sums[lane + j * 32] * (1.0f / 4096.0f);
        a0 = fmaf(sv, w1[(ob + 0) * 192 + lane + j * 32], a0);
        a1 = fmaf(sv, w1[(ob + 1) * 192 + lane + j * 32], a1);
        a2 = fmaf(sv, w1[(ob + 2) * 192 + lane + j * 32], a2);
        a3 = fmaf(sv, w1[(ob + 3) * 192 + lane + j * 32], a3);
    }
    #pragma unroll
    for (int off = 16; off; off >>= 1) {
        a0 += __shfl_xor_sync(FULLM, a0, off);
        a1 += __shfl_xor_sync(FULLM, a1, off);
        a2 += __shfl_xor_sync(FULLM, a2, off);
        a3 += __shfl_xor_sync(FULLM, a3, off);
    }
    if (lane == 0) {
        g_h[ob + 0] = fmaxf(a0 + b1[ob + 0], 0.f);
        g_h[ob + 1] = fmaxf(a1 + b1[ob + 1], 0.f);
        g_h[ob + 2] = fmaxf(a2 + b1[ob + 2], 0.f);
        g_h[ob + 3] = fmaxf(a3 + b1[ob + 3], 0.f);
    }
}

// ---------------- norm-MLP layer 2 -> g_mult; zeroes g_sums -------------------
__global__ void gamma2_kernel(const float* __restrict__ w2, const float* __restrict__ b2,
                              const float* __restrict__ scale) {
    const int warp = threadIdx.x >> 5, lane = threadIdx.x & 31;
    const int ob = blockIdx.x * 16 + warp * 4;
    float a0 = 0.f, a1 = 0.f, a2 = 0.f, a3 = 0.f;
    #pragma unroll
    for (int j = 0; j < 12; j++) {
        float hv = g_h[lane + j * 32];
        a0 = fmaf(hv, w2[(ob + 0) * 384 + lane + j * 32], a0);
        a1 = fmaf(hv, w2[(ob + 1) * 384 + lane + j * 32], a1);
        a2 = fmaf(hv, w2[(ob + 2) * 384 + lane + j * 32], a2);
        a3 = fmaf(hv, w2[(ob + 3) * 384 + lane + j * 32], a3);
    }
    #pragma unroll
    for (int off = 16; off; off >>= 1) {
        a0 += __shfl_xor_sync(FULLM, a0, off);
        a1 += __shfl_xor_sync(FULLM, a1, off);
        a2 += __shfl_xor_sync(FULLM, a2, off);
        a3 += __shfl_xor_sync(FULLM, a3, off);
    }
    if (lane == 0) {
        #pragma unroll
        for (int u = 0; u < 4; u++) {
            float a = (u == 0 ? a0 : u == 1 ? a1 : u == 2 ? a2 : a3) + b2[ob + u];
            float gamma = 1.f / (1.f + expf(-a));
            float rms = sqrtf(g_sums[192 + ob + u] * (1.0f / 4096.0f) + 1e-6f);
            g_mult[ob + u] = scale[ob + u] * gamma / rms;
            g_sums[ob + u] = 0.f;
            g_sums[192 + ob + u] = 0.f;
        }
    }
}

// ---------------- convwA: split qkv_w (x g_mult) + proj_w + mlp_w2 ------------
// 144 blocks x 256 thr; each thread 2 independent float4 items.
// Layout: [0,27648) qkv_w -> bank0 ; [27648,36864) proj_w -> bank1 ;
//         [36864,73728) mlp_w2 -> bank2.
__global__ void convwA_kernel(const float* __restrict__ qkvw, const float* __restrict__ projw,
                              const float* __restrict__ w2m) {
    int base = blockIdx.x * 256 + threadIdx.x;       // 0..36863
    #pragma unroll
    for (int s = 0; s < 2; s++) {
        int i4 = base + s * 36864;
        if (i4 < 27648) {                    // qkv_w: fold g_mult
            int idx = i4 * 4;
            float4 t = ((const float4*)qkvw)[i4];
            int m = idx % 192;
            t.x *= g_mult[m]; t.y *= g_mult[m + 1]; t.z *= g_mult[m + 2]; t.w *= g_mult[m + 3];
            split4(t, g_wb, g_wsm, idx);
        } else if (i4 < 36864) {             // proj_w
            int j = i4 - 27648;
            split4(((const float4*)projw)[j], g_wb2, g_ws2, j * 4);
        } else {                             // mlp_w2 (gamma-independent)
            int j = i4 - 36864;
            split4(((const float4*)w2m)[j], g_w3b, g_w3s, j * 4);
        }
    }
}

// ---------------- convwB: mlp_w1 (x g_mult) split + initout -------------------
// 456 blocks x 256 thr; each thread 2 independent items (stride 116736).
// initout reconstructs: out = (x2b + x2s) + bias.
__global__ void convwB_kernel(const float* __restrict__ w1,
                              const __nv_bfloat16* __restrict__ x2b,
                              const __nv_bfloat16* __restrict__ x2s,
                              const float* __restrict__ bias, float* __restrict__ out) {
    int base = blockIdx.x * 256 + threadIdx.x;       // 0..116735
    #pragma unroll
    for (int s = 0; s < 2; s++) {
        int i4 = base + s * 116736;
        if (i4 < 36864) {                    // mlp_w1: fold g_mult
            int idx = i4 * 4;
            float4 v = ((const float4*)w1)[i4];
            int m = idx % 192;
            v.x *= g_mult[m]; v.y *= g_mult[m + 1]; v.z *= g_mult[m + 2]; v.w *= g_mult[m + 3];
            split4(v, g_wb, g_wsm, idx);
        } else if (i4 < 233472) {            // initout (196608 float4s)
            int j = i4 - 36864;
            float b = bias[j >> 10];
            uint2 pb = *(const uint2*)(x2b + j * 4);
            uint2 psm = *(const uint2*)(x2s + j * 4);
            float2 b0 = __bfloat1622float2(*(__nv_bfloat162*)&pb.x);
            float2 b1 = __bfloat1622float2(*(__nv_bfloat162*)&pb.y);
            float2 s0 = __bfloat1622float2(*(__nv_bfloat162*)&psm.x);
            float2 s1 = __bfloat1622float2(*(__nv_bfloat162*)&psm.y);
            float4 v = make_float4(b0.x + s0.x + b, b0.y + s0.y + b,
                                   b1.x + s1.x + b, b1.y + s1.y + b);
            ((float4*)out)[j] = v;
        }
    }
}

// ---------------- GEMM v9: bf16x3 pairs, cp.async 3-stage ---------------------
// OUTM: 0 none/pairs-only, 2 atomicAdd (Co,N), 3 fp16 (N,Co) smem-staged.
template <int CI, int CIFULL, bool BNMAJ, int EPI, bool STATS, int OUTM, bool PAIRS, bool WF32>
__global__ void __launch_bounds__(128)
gemm_kernel(const __nv_bfloat16* __restrict__ Awb, const __nv_bfloat16* __restrict__ Aws,
            const __nv_bfloat16* __restrict__ Bxb, const __nv_bfloat16* __restrict__ Bxs,
            const float* __restrict__ bias, const float* __restrict__ res,
            float* __restrict__ out, __nv_bfloat16* __restrict__ pb,
            __nv_bfloat16* __restrict__ ps, int Co, int N) {
    constexpr int NK = CI / 16;
    constexpr int BW = BNMAJ ? (64 * 12) : (16 * 36);
    __shared__ uint sA[3][2][64 * 12];
    __shared__ uint sB[3][2][BW];
    __shared__ __half sT[(OUTM == 3) ? 64 * 72 : 8];

    const int bn = blockIdx.x * 64;
    const int bm = blockIdx.y * 64;
    const int kbase = blockIdx.z * CI;
    const int tid = threadIdx.x;
    const int warp = tid >> 5, lane = tid & 31;
    const int gid = lane >> 2, tig = lane & 3;
    const int wmb = (warp >> 1) * 32;
    const int wnb = (warp & 1) * 32;

    auto stage = [&](int t, int st) {
        const int kk = kbase + t * 16;
        {
            int row = tid >> 1, ch = tid & 1;
            size_t go = (size_t)(bm + row) * CIFULL + kk + ch * 8;
            cp16(smem_u32(&sA[st][0][row * 12 + ch * 4]), Awb + go);
            cp16(smem_u32(&sA[st][1][row * 12 + ch * 4]), Aws + go);
        }
        if (BNMAJ) {
            int row = tid >> 1, ch = tid & 1;
            size_t go = (size_t)(bn + row) * CIFULL + kk + ch * 8;
            cp16(smem_u32(&sB[st][0][row * 12 + ch * 4]), Bxb + go);
            cp16(smem_u32(&sB[st][1][row * 12 + ch * 4]), Bxs + go);
        } else {
            int row = tid >> 3, ch = tid & 7;
            size_t go = (size_t)(kk + row) * N + bn + ch * 8;
            cp16(smem_u32((char*)&sB[st][0][0] + row * 144 + ch * 16), Bxb + go);
            cp16(smem_u32((char*)&sB[st][1][0] + row * 144 + ch * 16), Bxs + go);
        }
        cp_commit();
    };

    float d[2][4][4];
    #pragma unroll
    for (int mt = 0; mt < 2; mt++)
        #pragma unroll
        for (int j = 0; j < 4; j++)
            #pragma unroll
            for (int e = 0; e < 4; e++) d[mt][j][e] = 0.f;

    stage(0, 0);
    stage(1, 1);

    #pragma unroll 1
    for (int t = 0; t < NK; t++) {
        const int st = t % 3;
        if (t == NK - 1) cp_wait<0>(); else cp_wait<1>();
        __syncthreads();

        unsigned Ab[2][4], As[2][4];
        #pragma unroll
        for (int mt = 0; mt < 2; mt++) {
            int m0 = wmb + 16 * mt + gid;
            Ab[mt][0] = sA[st][0][m0 * 12 + tig];
            Ab[mt][1] = sA[st][0][(m0 + 8) * 12 + tig];
            Ab[mt][2] = sA[st][0][m0 * 12 + tig + 4];
            Ab[mt][3] = sA[st][0][(m0 + 8) * 12 + tig + 4];
            As[mt][0] = sA[st][1][m0 * 12 + tig];
            As[mt][1] = sA[st][1][(m0 + 8) * 12 + tig];
            As[mt][2] = sA[st][1][m0 * 12 + tig + 4];
            As[mt][3] = sA[st][1][(m0 + 8) * 12 + tig + 4];
        }
        #pragma unroll
        for (int j = 0; j < 4; j++) {
            unsigned Bb[2], Bs[2];
            if (BNMAJ) {
                int n0 = wnb + 8 * j + gid;
                Bb[0] = sB[st][0][n0 * 12 + tig];
                Bb[1] = sB[st][0][n0 * 12 + tig + 4];
                Bs[0] = sB[st][1][n0 * 12 + tig];
                Bs[1] = sB[st][1][n0 * 12 + tig + 4];
            } else {
                int boff = ((lane & 15) * 72 + wnb + 8 * j) * 2;
                ldsm_x2_trans(Bb[0], Bb[1], smem_u32((char*)&sB[st][0][0] + boff));
                ldsm_x2_trans(Bs[0], Bs[1], smem_u32((char*)&sB[st][1][0] + boff));
            }
            #pragma unroll
            for (int mt = 0; mt < 2; mt++) {
                mma_bf16(d[mt][j], Ab[mt], Bb);
                mma_bf16(d[mt][j], As[mt], Bb);
                mma_bf16(d[mt][j], Ab[mt], Bs);
            }
        }
        if (t + 2 < NK) stage(t + 2, (t + 2) % 3);
    }

    // ---- epilogue ----
    const int gn0 = bn + wnb + 2 * tig;
    #pragma unroll
    for (int mt = 0; mt < 2; mt++) {
        #pragma unroll
        for (int half = 0; half < 2; half++) {
            int m = bm + wmb + 16 * mt + gid + 8 * half;
            float bv = (OUTM == 2) ? 0.f : bias[m];
            float v[8];
            #pragma unroll
            for (int j = 0; j < 4; j++) {
                v[2 * j]     = d[mt][j][2 * half]     + bv;
                v[2 * j + 1] = d[mt][j][2 * half + 1] + bv;
            }
            if (EPI == 1) {
                #pragma unroll
                for (int e = 0; e < 8; e++) {
                    float u = v[e];
                    v[e] = u * 0.5f * (1.f + erff(u * 0.70710678118654752f));
                }
            }
            if (EPI == 2) {
                #pragma unroll
                for (int j = 0; j < 4; j++) {
                    float2 r2 = *(const float2*)&res[(size_t)m * N + gn0 + 8 * j];
                    v[2 * j] += r2.x; v[2 * j + 1] += r2.y;
                }
            }
            if (STATS) {
                float ls = 0.f, ls2 = 0.f;
                #pragma unroll
                for (int e = 0; e < 8; e++) { ls += v[e]; ls2 = fmaf(v[e], v[e], ls2); }
                ls  += __shfl_xor_sync(FULLM, ls, 1);  ls  += __shfl_xor_sync(FULLM, ls, 2);
                ls2 += __shfl_xor_sync(FULLM, ls2, 1); ls2 += __shfl_xor_sync(FULLM, ls2, 2);
                if (tig == 0) {
                    atomicAdd(&g_sums[m], ls);
                    atomicAdd(&g_sums[192 + m], ls2);
                }
            }
            if (PAIRS) {
                #pragma unroll
                for (int j = 0; j < 4; j++)
                    store_pair(pb, ps, (size_t)m * N + gn0 + 8 * j, v[2 * j], v[2 * j + 1]);
            }
            if (OUTM == 3) {
                int ml = wmb + 16 * mt + gid + 8 * half;
                #pragma unroll
                for (int j = 0; j < 4; j++) {
                    int nl = wnb + 2 * tig + 8 * j;
                    sT[nl * 72 + ml]       = __float2half(v[2 * j]);
                    sT[(nl + 1) * 72 + ml] = __float2half(v[2 * j + 1]);
                }
            } else if (OUTM == 2) {
                #pragma unroll
                for (int j = 0; j < 4; j++) {
                    atomicAdd(&out[(size_t)m * N + gn0 + 8 * j],     v[2 * j]);
                    atomicAdd(&out[(size_t)m * N + gn0 + 8 * j + 1], v[2 * j + 1]);
                }
            } else if (WF32) {
                #pragma unroll
                for (int j = 0; j < 4; j++)
                    *(float2*)&out[(size_t)m * N + gn0 + 8 * j] = make_float2(v[2 * j], v[2 * j + 1]);
            }
        }
    }
    if (OUTM == 3) {
        __syncthreads();
        __half* oh = (__half*)out;
        #pragma unroll
        for (int i = 0; i < 4; i++) {
            int idx = tid + i * 128;
            int row = idx >> 3, ch = idx & 7;
            *(uint4*)(oh + (size_t)(bn + row) * Co + bm + ch * 8) =
                *(const uint4*)(sT + row * 72 + ch * 8);
        }
    }
}

// ---------------- 3D neighborhood attention (fp16, cp.async staging) ----------
__global__ void __launch_bounds__(256) attn_kernel(const __half* __restrict__ qkvh,
                                                   __nv_bfloat16* __restrict__ obb,
                                                   __nv_bfloat16* __restrict__ obs) {
    extern __shared__ __align__(16) half2 sKV[];   // sK[8192] then sV[8192]
    half2* sK = sKV;
    half2* sV = sKV + 8192;

    const int tile = blockIdx.x, head = blockIdx.y;
    const int tid = threadIdx.x;

    const int Td = ((tile >> 4) & 3) * 4, Th = ((tile >> 2) & 3) * 4, Tw = (tile & 3) * 4;
    const int Bd = min(max(Td - 2, 0), 8);
    const int Bh = min(max(Th - 2, 0), 8);
    const int Bw = min(max(Tw - 2, 0), 8);

    // ---- stage K and V via cp.async; overlap Q load + index math ----
    #pragma unroll
    for (int it = 0; it < 16; it++) {
        int i = tid + it * 256;
        int row = i >> 3, g = i & 7;
        int rd = row >> 6, rh = (row >> 3) & 7, rw = row & 7;
        int gpos = ((Bd + rd) << 8) + ((Bh + rh) << 4) + (Bw + rw);
        int mat = g >> 2, c = g & 3;
        const __half* src = qkvh + (size_t)gpos * 576 + 192 + 192 * mat + head * 32 + c * 8;
        half2* dst = (mat ? sV : sK) + row * 16 + c * 4;
        cp16(smem_u32(dst), src);
    }
    cp_commit();

    const int quarter = tid & 3, vox = tid >> 2;
    const int aw = vox & 3, ah = (vox >> 2) & 3, ad = vox >> 4;
    const int vd = Td + ad, vh = Th + ah, vw = Tw + aw;
    const int gv = (vd << 8) + (vh << 4) + vw;
    const int ld = min(max(vd - 2, 0), 11) - Bd;
    const int lh = min(max(vh - 2, 0), 11) - Bh;
    const int lw = min(max(vw - 2, 0), 11) - Bw;
    const int rbase = ld * 64 + lh * 8 + lw;
    const int lane = tid & 31;

    float q[8];
    {
        const __half* qp = qkvh + (size_t)gv * 576 + head * 32 + quarter * 8;
        uint4 qq = *(const uint4*)qp;
        const half2* qh = (const half2*)&qq;
        #pragma unroll
        for (int c = 0; c < 4; c++) {
            float2 f = __half22float2(qh[c]);
            q[2 * c]     = f.x * 0.17677669529663687f;
            q[2 * c + 1] = f.y * 0.17677669529663687f;
        }
    }
    cp_wait<0>();
    __syncthreads();

    float sc[32];
    #pragma unroll
    for (int i = 0; i < 32; i++) sc[i] = -1e30f;

    #pragma unroll
    for (int j = 0; j < 125; j++) {
        const int a = j / 25, b = (j / 5) % 5, c5 = j % 5;
        int row = rbase + a * 64 + b * 8 + c5;
        uint4 kk = *(const uint4*)(sK + row * 16 + quarter * 4);
        float2 f0 = __half22float2(*reinterpret_cast<half2*>(&kk.x));
        float2 f1 = __half22float2(*reinterpret_cast<half2*>(&kk.y));
        float2 f2 = __half22float2(*reinterpret_cast<half2*>(&kk.z));
        float2 f3 = __half22float2(*reinterpret_cast<half2*>(&kk.w));
        float p = q[0] * f0.x;
        p = fmaf(q[1], f0.y, p); p = fmaf(q[2], f1.x, p); p = fmaf(q[3], f1.y, p);
        p = fmaf(q[4], f2.x, p); p = fmaf(q[5], f2.y, p);
        p = fmaf(q[6], f3.x, p); p = fmaf(q[7], f3.y, p);
        p += __shfl_xor_sync(FULLM, p, 1);
        p += __shfl_xor_sync(FULLM, p, 2);
        if ((j & 3) == quarter) sc[j >> 2] = p;
    }

    float mx = -1e30f;
    #pragma unroll
    for (int i = 0; i < 32; i++) mx = fmaxf(mx, sc[i]);
    mx = fmaxf(mx, __shfl_xor_sync(FULLM, mx, 1));
    mx = fmaxf(mx, __shfl_xor_sync(FULLM, mx, 2));
    float tot = 0.f;
    #pragma unroll
    for (int i = 0; i < 32; i++) { sc[i] = __expf(sc[i] - mx); tot += sc[i]; }
    tot += __shfl_xor_sync(FULLM, tot, 1);
    tot += __shfl_xor_sync(FULLM, tot, 2);
    float inv = 1.f / tot;

    float o8[8] = {0.f, 0.f, 0.f, 0.f, 0.f, 0.f, 0.f, 0.f};
    #pragma unroll
    for (int j = 0; j < 125; j++) {
        const int a = j / 25, b = (j / 5) % 5, c5 = j % 5;
        float p = __shfl_sync(FULLM, sc[j >> 2], (lane & ~3) | (j & 3));
        int row = rbase + a * 64 + b * 8 + c5;
        uint4 vvp = *(const uint4*)(sV + row * 16 + quarter * 4);
        float2 f0 = __half22float2(*reinterpret_cast<half2*>(&vvp.x));
        float2 f1 = __half22float2(*reinterpret_cast<half2*>(&vvp.y));
        float2 f2 = __half22float2(*reinterpret_cast<half2*>(&vvp.z));
        float2 f3 = __half22float2(*reinterpret_cast<half2*>(&vvp.w));
        o8[0] = fmaf(p, f0.x, o8[0]); o8[1] = fmaf(p, f0.y, o8[1]);
        o8[2] = fmaf(p, f1.x, o8[2]); o8[3] = fmaf(p, f1.y, o8[3]);
        o8[4] = fmaf(p, f2.x, o8[4]); o8[5] = fmaf(p, f2.y, o8[5]);
        o8[6] = fmaf(p, f3.x, o8[6]); o8[7] = fmaf(p, f3.y, o8[7]);
    }
    size_t ob0 = (size_t)gv * 192 + head * 32 + quarter * 8;
    #pragma unroll
    for (int c = 0; c < 4; c++)
        store_pair(obb, obs, ob0 + 2 * c, o8[2 * c] * inv, o8[2 * c + 1] * inv);
}

// ---------------- orchestration ----------------------------------------------
extern "C" void kernel_launch(void* const* d_in, const int* in_sizes, int n_in,
                              void* d_out, int out_size) {
    const float* x      = (const float*)d_in[0];
    const float* scale1 = (const float*)d_in[1];
    const float* n1_w1  = (const float*)d_in[2];
    const float* n1_b1  = (const float*)d_in[3];
    const float* n1_w2  = (const float*)d_in[4];
    const float* n1_b2  = (const float*)d_in[5];
    const float* qkv_w  = (const float*)d_in[6];
    const float* qkv_b  = (const float*)d_in[7];
    const float* proj_w = (const float*)d_in[8];
    const float* proj_b = (const float*)d_in[9];
    const float* scale2 = (const float*)d_in[10];
    const float* n2_w1  = (const float*)d_in[11];
    const float* n2_b1  = (const float*)d_in[12];
    const float* n2_w2  = (const float*)d_in[13];
    const float* n2_b2  = (const float*)d_in[14];
    const float* mlp_w1 = (const float*)d_in[15];
    const float* mlp_b1 = (const float*)d_in[16];
    const float* mlp_w2 = (const float*)d_in[17];
    const float* mlp_b2 = (const float*)d_in[18];
    float* out = (float*)d_out;

    __half* qkvh;
    __nv_bfloat16 *wb, *wsm, *wb2, *ws2, *w3b, *w3s, *xb, *xs, *obb, *obs, *x2b, *x2s, *mbb, *mbs;
    cudaGetSymbolAddress((void**)&qkvh, g_qkvh);
    cudaGetSymbolAddress((void**)&wb,  g_wb);
    cudaGetSymbolAddress((void**)&wsm, g_wsm);
    cudaGetSymbolAddress((void**)&wb2, g_wb2);
    cudaGetSymbolAddress((void**)&ws2, g_ws2);
    cudaGetSymbolAddress((void**)&w3b, g_w3b);
    cudaGetSymbolAddress((void**)&w3s, g_w3s);
    cudaGetSymbolAddress((void**)&xb,  g_xb);
    cudaGetSymbolAddress((void**)&xs,  g_xs);
    cudaGetSymbolAddress((void**)&obb, g_obb);
    cudaGetSymbolAddress((void**)&obs, g_obs);
    cudaGetSymbolAddress((void**)&x2b, g_x2b);
    cudaGetSymbolAddress((void**)&x2s, g_x2s);
    cudaGetSymbolAddress((void**)&mbb, g_mbb);
    cudaGetSymbolAddress((void**)&mbs, g_mbs);

    cudaFuncSetAttribute(attn_kernel, cudaFuncAttributeMaxDynamicSharedMemorySize, 65536);

    // ---- stage A ----
    colstats_kernel<<<192, 256>>>(x, xb, xs);                        // 1
    gamma1_kernel<<<24, 128>>>(n1_w1, n1_b1);                        // 2
    gamma2_kernel<<<12, 128>>>(n1_w2, n1_b2, scale1);                // 3 (zeroes g_sums)
    convwA_kernel<<<144, 256>>>(qkv_w, proj_w, mlp_w2);              // 4

    // qkv -> fp16 (pos,576), smem-staged coalesced transpose stores // 5
    gemm_kernel<192, 192, false, 0, false, 3, false, false><<<dim3(64, 9), 128>>>(
        wb, wsm, xb, xs, qkv_b, nullptr, (float*)qkvh, nullptr, nullptr, 576, NPOS);

    // attention (fp16 in, cp.async staging) -> ob bf16 pairs (N,C)  // 6
    attn_kernel<<<dim3(64, 6), 256, 65536>>>(qkvh, obb, obs);

    // proj + residual + stage-B stats -> x2 bf16 pairs only         // 7
    gemm_kernel<192, 192, true, 2, true, 0, true, false><<<dim3(64, 3), 128>>>(
        wb2, ws2, obb, obs, proj_b, x, nullptr, x2b, x2s, 192, NPOS);

    // ---- stage B ----
    gamma1_kernel<<<24, 128>>>(n2_w1, n2_b1);                        // 8
    gamma2_kernel<<<12, 128>>>(n2_w2, n2_b2, scale2);                // 9 (zeroes g_sums)
    convwB_kernel<<<456, 256>>>(mlp_w1, x2b, x2s, mlp_b2, out);      // 10 (w1 split + initout)

    // mlp1 + gelu -> mb bf16 pairs                                  // 11
    gemm_kernel<192, 192, false, 1, false, 0, true, false><<<dim3(64, 12), 128>>>(
        wb, wsm, x2b, x2s, mlp_b1, nullptr, nullptr, mbb, mbs, 768, NPOS);

    // mlp2 split-K x4 atomic-accumulate into pre-initialized out    // 12
    gemm_kernel<192, 768, false, 0, false, 2, false, false><<<dim3(64, 3, 4), 128>>>(
        w3b, w3s, mbb, mbs, mlp_b2, nullptr, out, nullptr, nullptr, 192, NPOS);
}

// round 15
// speedup vs baseline: 1.1412x; 1.0392x over previous
#include <cuda_runtime.h>
#include <cuda_fp16.h>
#include <cuda_bf16.h>
#include <math.h>

#define NPOS 4096
#define FULLM 0xffffffffu

// ---------------- scratch (static device globals; no allocation) -------------
__device__ __half g_qkvh[NPOS * 576];          // (pos, 576) pos-major fp16
__device__ float g_sums[2 * 192];              // per-channel sum / sumsq
__device__ float g_mult[192];                  // scale*gamma/rms
__device__ float g_h[384];                     // norm-MLP hidden
// bf16 big/small pairs
__device__ __nv_bfloat16 g_wb [768 * 192],  g_wsm[768 * 192];    // W bank 0 (qkv, then mlp_w1)
__device__ __nv_bfloat16 g_wb2[192 * 768],  g_ws2[192 * 768];    // W bank 1 (proj)
__device__ __nv_bfloat16 g_w3b[192 * 768],  g_w3s[192 * 768];    // W bank 2 (mlp_w2)
__device__ __nv_bfloat16 g_xb [192 * NPOS], g_xs [192 * NPOS];   // x pairs (C,N)
__device__ __nv_bfloat16 g_obb[NPOS * 192], g_obs[NPOS * 192];   // attn out pairs (N,C)
__device__ __nv_bfloat16 g_x2b[192 * NPOS], g_x2s[192 * NPOS];   // x2 pairs (C,N)
__device__ __nv_bfloat16 g_mbb[768 * NPOS], g_mbs[768 * NPOS];   // mlp hidden pairs (C,N)

// ---------------- helpers -----------------------------------------------------
__device__ __forceinline__ unsigned smem_u32(const void* p) {
    return (unsigned)__cvta_generic_to_shared(p);
}
__device__ __forceinline__ void cp16(unsigned dst, const void* src) {
    asm volatile("cp.async.cg.shared.global [%0], [%1], 16;" :: "r"(dst), "l"(src));
}
__device__ __forceinline__ void cp_commit() { asm volatile("cp.async.commit_group;"); }
template <int W> __device__ __forceinline__ void cp_wait() {
    asm volatile("cp.async.wait_group %0;" :: "n"(W));
}
__device__ __forceinline__ void mma_bf16(float* d, const unsigned* a, const unsigned* b) {
    asm volatile(
        "mma.sync.aligned.m16n8k16.row.col.f32.bf16.bf16.f32 "
        "{%0,%1,%2,%3},{%4,%5,%6,%7},{%8,%9},{%0,%1,%2,%3};"
        : "+f"(d[0]), "+f"(d[1]), "+f"(d[2]), "+f"(d[3])
        : "r"(a[0]), "r"(a[1]), "r"(a[2]), "r"(a[3]), "r"(b[0]), "r"(b[1]));
}
__device__ __forceinline__ void ldsm_x2_trans(unsigned& r0, unsigned& r1, unsigned addr) {
    asm volatile("ldmatrix.sync.aligned.m8n8.x2.trans.shared.b16 {%0,%1}, [%2];"
                 : "=r"(r0), "=r"(r1) : "r"(addr));
}
__device__ __forceinline__ void store_pair(__nv_bfloat16* pb, __nv_bfloat16* ps,
                                           size_t idx, float v0, float v1) {
    __nv_bfloat16 b0 = __float2bfloat16_rn(v0), b1 = __float2bfloat16_rn(v1);
    __nv_bfloat16 s0 = __float2bfloat16_rn(v0 - __bfloat162float(b0));
    __nv_bfloat16 s1 = __float2bfloat16_rn(v1 - __bfloat162float(b1));
    *(__nv_bfloat162*)(pb + idx) = __halves2bfloat162(b0, b1);
    *(__nv_bfloat162*)(ps + idx) = __halves2bfloat162(s0, s1);
}
__device__ __forceinline__ void split4(float4 v, __nv_bfloat16* db, __nv_bfloat16* ds, int idx) {
    __nv_bfloat16 b0 = __float2bfloat16_rn(v.x), b1 = __float2bfloat16_rn(v.y);
    __nv_bfloat16 b2 = __float2bfloat16_rn(v.z), b3 = __float2bfloat16_rn(v.w);
    *(__nv_bfloat162*)(db + idx)     = __halves2bfloat162(b0, b1);
    *(__nv_bfloat162*)(db + idx + 2) = __halves2bfloat162(b2, b3);
    *(__nv_bfloat162*)(ds + idx) = __halves2bfloat162(
        __float2bfloat16_rn(v.x - __bfloat162float(b0)),
        __float2bfloat16_rn(v.y - __bfloat162float(b1)));
    *(__nv_bfloat162*)(ds + idx + 2) = __halves2bfloat162(
        __float2bfloat16_rn(v.z - __bfloat162float(b2)),
        __float2bfloat16_rn(v.w - __bfloat162float(b3)));
}

// ---------------- per-channel stats over x + bf16 pair conversion -------------
__global__ void colstats_kernel(const float* __restrict__ x,
                                __nv_bfloat16* __restrict__ xb,
                                __nv_bfloat16* __restrict__ xs) {
    int c = blockIdx.x;
    const float* p = x + c * NPOS;
    float s = 0.f, s2 = 0.f;
    for (int i = threadIdx.x; i < NPOS; i += 256) {
        float v = p[i];
        s += v;
        s2 = fmaf(v, v, s2);
        __nv_bfloat16 b = __float2bfloat16_rn(v);
        xb[c * NPOS + i] = b;
        xs[c * NPOS + i] = __float2bfloat16_rn(v - __bfloat162float(b));
    }
    __shared__ float sh0[256], sh1[256];
    sh0[threadIdx.x] = s; sh1[threadIdx.x] = s2;
    __syncthreads();
    for (int o = 128; o > 0; o >>= 1) {
        if (threadIdx.x < o) {
            sh0[threadIdx.x] += sh0[threadIdx.x + o];
            sh1[threadIdx.x] += sh1[threadIdx.x + o];
        }
        __syncthreads();
    }
    if (threadIdx.x == 0) {
        g_sums[c]       = sh0[0];
        g_sums[192 + c] = sh1[0];
    }
}

// ---------------- norm-MLP layer 1 --------------------------------------------
__global__ void gamma1_kernel(const float* __restrict__ w1, const float* __restrict__ b1) {
    const int warp = threadIdx.x >> 5, lane = threadIdx.x & 31;
    const int ob = blockIdx.x * 16 + warp * 4;
    float a0 = 0.f, a1 = 0.f, a2 = 0.f, a3 = 0.f;
    #pragma unroll
    for (int j = 0; j < 6; j++) {
        float sv = g_sums[lane + j * 32] * (1.0f / 4096.0f);
        a0 = fmaf(sv, w1[(ob + 0) * 192 + lane + j * 32], a0);
        a1 = fmaf(sv, w1[(ob + 1) * 192 + lane + j * 32], a1);
        a2 = fmaf(sv, w1[(ob + 2) * 192 + lane + j * 32], a2);
        a3 = fmaf(sv, w1[(ob + 3) * 192 + lane + j * 32], a3);
    }
    #pragma unroll
    for (int off = 16; off; off >>= 1) {
        a0 += __shfl_xor_sync(FULLM, a0, off);
        a1 += __shfl_xor_sync(FULLM, a1, off);
        a2 += __shfl_xor_sync(FULLM, a2, off);
        a3 += __shfl_xor_sync(FULLM, a3, off);
    }
    if (lane == 0) {
        g_h[ob + 0] = fmaxf(a0 + b1[ob + 0], 0.f);
        g_h[ob + 1] = fmaxf(a1 + b1[ob + 1], 0.f);
        g_h[ob + 2] = fmaxf(a2 + b1[ob + 2], 0.f);
        g_h[ob + 3] = fmaxf(a3 + b1[ob + 3], 0.f);
    }
}

// ---------------- norm-MLP layer 2 -> g_mult; zeroes g_sums -------------------
__global__ void gamma2_kernel(const float* __restrict__ w2, const float* __restrict__ b2,
                              const float* __restrict__ scale) {
    const int warp = threadIdx.x >> 5, lane = threadIdx.x & 31;
    const int ob = blockIdx.x * 16 + warp * 4;
    float a0 = 0.f, a1 = 0.f, a2 = 0.f, a3 = 0.f;
    #pragma unroll
    for (int j = 0; j < 12; j++) {
        float hv = g_h[lane + j * 32];
        a0 = fmaf(hv, w2[(ob + 0) * 384 + lane + j * 32], a0);
        a1 = fmaf(hv, w2[(ob + 1) * 384 + lane + j * 32], a1);
        a2 = fmaf(hv, w2[(ob + 2) * 384 + lane + j * 32], a2);
        a3 = fmaf(hv, w2[(ob + 3) * 384 + lane + j * 32], a3);
    }
    #pragma unroll
    for (int off = 16; off; off >>= 1) {
        a0 += __shfl_xor_sync(FULLM, a0, off);
        a1 += __shfl_xor_sync(FULLM, a1, off);
        a2 += __shfl_xor_sync(FULLM, a2, off);
        a3 += __shfl_xor_sync(FULLM, a3, off);
    }
    if (lane == 0) {
        #pragma unroll
        for (int u = 0; u < 4; u++) {
            float a = (u == 0 ? a0 : u == 1 ? a1 : u == 2 ? a2 : a3) + b2[ob + u];
            float gamma = 1.f / (1.f + expf(-a));
            float rms = sqrtf(g_sums[192 + ob + u] * (1.0f / 4096.0f) + 1e-6f);
            g_mult[ob + u] = scale[ob + u] * gamma / rms;
            g_sums[ob + u] = 0.f;
            g_sums[192 + ob + u] = 0.f;
        }
    }
}

// ---------------- convwA: split qkv_w (x g_mult) + proj_w + mlp_w2 ------------
__global__ void convwA_kernel(const float* __restrict__ qkvw, const float* __restrict__ projw,
                              const float* __restrict__ w2m) {
    int base = blockIdx.x * 256 + threadIdx.x;       // 0..36863
    #pragma unroll
    for (int s = 0; s < 2; s++) {
        int i4 = base + s * 36864;
        if (i4 < 27648) {                    // qkv_w: fold g_mult
            int idx = i4 * 4;
            float4 t = ((const float4*)qkvw)[i4];
            int m = idx % 192;
            t.x *= g_mult[m]; t.y *= g_mult[m + 1]; t.z *= g_mult[m + 2]; t.w *= g_mult[m + 3];
            split4(t, g_wb, g_wsm, idx);
        } else if (i4 < 36864) {             // proj_w
            int j = i4 - 27648;
            split4(((const float4*)projw)[j], g_wb2, g_ws2, j * 4);
        } else {                             // mlp_w2 (gamma-independent)
            int j = i4 - 36864;
            split4(((const float4*)w2m)[j], g_w3b, g_w3s, j * 4);
        }
    }
}

// ---------------- convwB: mlp_w1 (x g_mult) split + initout -------------------
__global__ void convwB_kernel(const float* __restrict__ w1,
                              const __nv_bfloat16* __restrict__ x2b,
                              const __nv_bfloat16* __restrict__ x2s,
                              const float* __restrict__ bias, float* __restrict__ out) {
    int base = blockIdx.x * 256 + threadIdx.x;       // 0..116735
    #pragma unroll
    for (int s = 0; s < 2; s++) {
        int i4 = base + s * 116736;
        if (i4 < 36864) {                    // mlp_w1: fold g_mult
            int idx = i4 * 4;
            float4 v = ((const float4*)w1)[i4];
            int m = idx % 192;
            v.x *= g_mult[m]; v.y *= g_mult[m + 1]; v.z *= g_mult[m + 2]; v.w *= g_mult[m + 3];
            split4(v, g_wb, g_wsm, idx);
        } else if (i4 < 233472) {            // initout (196608 float4s)
            int j = i4 - 36864;
            float b = bias[j >> 10];
            uint2 pb = *(const uint2*)(x2b + j * 4);
            uint2 psm = *(const uint2*)(x2s + j * 4);
            float2 b0 = __bfloat1622float2(*(__nv_bfloat162*)&pb.x);
            float2 b1 = __bfloat1622float2(*(__nv_bfloat162*)&pb.y);
            float2 s0 = __bfloat1622float2(*(__nv_bfloat162*)&psm.x);
            float2 s1 = __bfloat1622float2(*(__nv_bfloat162*)&psm.y);
            float4 v = make_float4(b0.x + s0.x + b, b0.y + s0.y + b,
                                   b1.x + s1.x + b, b1.y + s1.y + b);
            ((float4*)out)[j] = v;
        }
    }
}

// ---------------- GEMM v9: bf16x3 pairs, cp.async 3-stage ---------------------
template <int CI, int CIFULL, bool BNMAJ, int EPI, bool STATS, int OUTM, bool PAIRS, bool WF32>
__global__ void __launch_bounds__(128)
gemm_kernel(const __nv_bfloat16* __restrict__ Awb, const __nv_bfloat16* __restrict__ Aws,
            const __nv_bfloat16* __restrict__ Bxb, const __nv_bfloat16* __restrict__ Bxs,
            const float* __restrict__ bias, const float* __restrict__ res,
            float* __restrict__ out, __nv_bfloat16* __restrict__ pb,
            __nv_bfloat16* __restrict__ ps, int Co, int N) {
    constexpr int NK = CI / 16;
    constexpr int BW = BNMAJ ? (64 * 12) : (16 * 36);
    __shared__ uint sA[3][2][64 * 12];
    __shared__ uint sB[3][2][BW];
    __shared__ __half sT[(OUTM == 3) ? 64 * 72 : 8];

    const int bn = blockIdx.x * 64;
    const int bm = blockIdx.y * 64;
    const int kbase = blockIdx.z * CI;
    const int tid = threadIdx.x;
    const int warp = tid >> 5, lane = tid & 31;
    const int gid = lane >> 2, tig = lane & 3;
    const int wmb = (warp >> 1) * 32;
    const int wnb = (warp & 1) * 32;

    auto stage = [&](int t, int st) {
        const int kk = kbase + t * 16;
        {
            int row = tid >> 1, ch = tid & 1;
            size_t go = (size_t)(bm + row) * CIFULL + kk + ch * 8;
            cp16(smem_u32(&sA[st][0][row * 12 + ch * 4]), Awb + go);
            cp16(smem_u32(&sA[st][1][row * 12 + ch * 4]), Aws + go);
        }
        if (BNMAJ) {
            int row = tid >> 1, ch = tid & 1;
            size_t go = (size_t)(bn + row) * CIFULL + kk + ch * 8;
            cp16(smem_u32(&sB[st][0][row * 12 + ch * 4]), Bxb + go);
            cp16(smem_u32(&sB[st][1][row * 12 + ch * 4]), Bxs + go);
        } else {
            int row = tid >> 3, ch = tid & 7;
            size_t go = (size_t)(kk + row) * N + bn + ch * 8;
            cp16(smem_u32((char*)&sB[st][0][0] + row * 144 + ch * 16), Bxb + go);
            cp16(smem_u32((char*)&sB[st][1][0] + row * 144 + ch * 16), Bxs + go);
        }
        cp_commit();
    };

    float d[2][4][4];
    #pragma unroll
    for (int mt = 0; mt < 2; mt++)
        #pragma unroll
        for (int j = 0; j < 4; j++)
            #pragma unroll
            for (int e = 0; e < 4; e++) d[mt][j][e] = 0.f;

    stage(0, 0);
    stage(1, 1);

    #pragma unroll 1
    for (int t = 0; t < NK; t++) {
        const int st = t % 3;
        if (t == NK - 1) cp_wait<0>(); else cp_wait<1>();
        __syncthreads();

        unsigned Ab[2][4], As[2][4];
        #pragma unroll
        for (int mt = 0; mt < 2; mt++) {
            int m0 = wmb + 16 * mt + gid;
            Ab[mt][0] = sA[st][0][m0 * 12 + tig];
            Ab[mt][1] = sA[st][0][(m0 + 8) * 12 + tig];
            Ab[mt][2] = sA[st][0][m0 * 12 + tig + 4];
            Ab[mt][3] = sA[st][0][(m0 + 8) * 12 + tig + 4];
            As[mt][0] = sA[st][1][m0 * 12 + tig];
            As[mt][1] = sA[st][1][(m0 + 8) * 12 + tig];
            As[mt][2] = sA[st][1][m0 * 12 + tig + 4];
            As[mt][3] = sA[st][1][(m0 + 8) * 12 + tig + 4];
        }
        #pragma unroll
        for (int j = 0; j < 4; j++) {
            unsigned Bb[2], Bs[2];
            if (BNMAJ) {
                int n0 = wnb + 8 * j + gid;
                Bb[0] = sB[st][0][n0 * 12 + tig];
                Bb[1] = sB[st][0][n0 * 12 + tig + 4];
                Bs[0] = sB[st][1][n0 * 12 + tig];
                Bs[1] = sB[st][1][n0 * 12 + tig + 4];
            } else {
                int boff = ((lane & 15) * 72 + wnb + 8 * j) * 2;
                ldsm_x2_trans(Bb[0], Bb[1], smem_u32((char*)&sB[st][0][0] + boff));
                ldsm_x2_trans(Bs[0], Bs[1], smem_u32((char*)&sB[st][1][0] + boff));
            }
            #pragma unroll
            for (int mt = 0; mt < 2; mt++) {
                mma_bf16(d[mt][j], Ab[mt], Bb);
                mma_bf16(d[mt][j], As[mt], Bb);
                mma_bf16(d[mt][j], Ab[mt], Bs);
            }
        }
        if (t + 2 < NK) stage(t + 2, (t + 2) % 3);
    }

    // ---- epilogue ----
    const int gn0 = bn + wnb + 2 * tig;
    #pragma unroll
    for (int mt = 0; mt < 2; mt++) {
        #pragma unroll
        for (int half = 0; half < 2; half++) {
            int m = bm + wmb + 16 * mt + gid + 8 * half;
            float bv = (OUTM == 2) ? 0.f : bias[m];
            float v[8];
            #pragma unroll
            for (int j = 0; j < 4; j++) {
                v[2 * j]     = d[mt][j][2 * half]     + bv;
                v[2 * j + 1] = d[mt][j][2 * half + 1] + bv;
            }
            if (EPI == 1) {
                #pragma unroll
                for (int e = 0; e < 8; e++) {
                    float u = v[e];
                    v[e] = u * 0.5f * (1.f + erff(u * 0.70710678118654752f));
                }
            }
            if (EPI == 2) {
                #pragma unroll
                for (int j = 0; j < 4; j++) {
                    float2 r2 = *(const float2*)&res[(size_t)m * N + gn0 + 8 * j];
                    v[2 * j] += r2.x; v[2 * j + 1] += r2.y;
                }
            }
            if (STATS) {
                float ls = 0.f, ls2 = 0.f;
                #pragma unroll
                for (int e = 0; e < 8; e++) { ls += v[e]; ls2 = fmaf(v[e], v[e], ls2); }
                ls  += __shfl_xor_sync(FULLM, ls, 1);  ls  += __shfl_xor_sync(FULLM, ls, 2);
                ls2 += __shfl_xor_sync(FULLM, ls2, 1); ls2 += __shfl_xor_sync(FULLM, ls2, 2);
                if (tig == 0) {
                    atomicAdd(&g_sums[m], ls);
                    atomicAdd(&g_sums[192 + m], ls2);
                }
            }
            if (PAIRS) {
                #pragma unroll
                for (int j = 0; j < 4; j++)
                    store_pair(pb, ps, (size_t)m * N + gn0 + 8 * j, v[2 * j], v[2 * j + 1]);
            }
            if (OUTM == 3) {
                int ml = wmb + 16 * mt + gid + 8 * half;
                #pragma unroll
                for (int j = 0; j < 4; j++) {
                    int nl = wnb + 2 * tig + 8 * j;
                    sT[nl * 72 + ml]       = __float2half(v[2 * j]);
                    sT[(nl + 1) * 72 + ml] = __float2half(v[2 * j + 1]);
                }
            } else if (OUTM == 2) {
                #pragma unroll
                for (int j = 0; j < 4; j++) {
                    atomicAdd(&out[(size_t)m * N + gn0 + 8 * j],     v[2 * j]);
                    atomicAdd(&out[(size_t)m * N + gn0 + 8 * j + 1], v[2 * j + 1]);
                }
            } else if (WF32) {
                #pragma unroll
                for (int j = 0; j < 4; j++)
                    *(float2*)&out[(size_t)m * N + gn0 + 8 * j] = make_float2(v[2 * j], v[2 * j + 1]);
            }
        }
    }
    if (OUTM == 3) {
        __syncthreads();
        __half* oh = (__half*)out;
        #pragma unroll
        for (int i = 0; i < 4; i++) {
            int idx = tid + i * 128;
            int row = idx >> 3, ch = idx & 7;
            *(uint4*)(oh + (size_t)(bn + row) * Co + bm + ch * 8) =
                *(const uint4*)(sT + row * 72 + ch * 8);
        }
    }
}

// ---------------- 3D neighborhood attention (fp16, HFMA2 math) ----------------
__global__ void __launch_bounds__(256) attn_kernel(const __half* __restrict__ qkvh,
                                                   __nv_bfloat16* __restrict__ obb,
                                                   __nv_bfloat16* __restrict__ obs) {
    extern __shared__ __align__(16) half2 sKV[];   // sK[8192] then sV[8192]
    half2* sK = sKV;
    half2* sV = sKV + 8192;

    const int tile = blockIdx.x, head = blockIdx.y;
    const int tid = threadIdx.x;

    const int Td = ((tile >> 4) & 3) * 4, Th = ((tile >> 2) & 3) * 4, Tw = (tile & 3) * 4;
    const int Bd = min(max(Td - 2, 0), 8);
    const int Bh = min(max(Th - 2, 0), 8);
    const int Bw = min(max(Tw - 2, 0), 8);

    // ---- stage K and V via cp.async; overlap Q load + index math ----
    #pragma unroll
    for (int it = 0; it < 16; it++) {
        int i = tid + it * 256;
        int row = i >> 3, g = i & 7;
        int rd = row >> 6, rh = (row >> 3) & 7, rw = row & 7;
        int gpos = ((Bd + rd) << 8) + ((Bh + rh) << 4) + (Bw + rw);
        int mat = g >> 2, c = g & 3;
        const __half* src = qkvh + (size_t)gpos * 576 + 192 + 192 * mat + head * 32 + c * 8;
        half2* dst = (mat ? sV : sK) + row * 16 + c * 4;
        cp16(smem_u32(dst), src);
    }
    cp_commit();

    const int quarter = tid & 3, vox = tid >> 2;
    const int aw = vox & 3, ah = (vox >> 2) & 3, ad = vox >> 4;
    const int vd = Td + ad, vh = Th + ah, vw = Tw + aw;
    const int gv = (vd << 8) + (vh << 4) + vw;
    const int ld = min(max(vd - 2, 0), 11) - Bd;
    const int lh = min(max(vh - 2, 0), 11) - Bh;
    const int lw = min(max(vw - 2, 0), 11) - Bw;
    const int rbase = ld * 64 + lh * 8 + lw;
    const int lane = tid & 31;

    // Q pre-scaled in half2
    half2 q2[4];
    {
        const __half* qp = qkvh + (size_t)gv * 576 + head * 32 + quarter * 8;
        uint4 qq = *(const uint4*)qp;
        const half2* qh = (const half2*)&qq;
        half2 s2 = __float2half2_rn(0.17677669529663687f);
        #pragma unroll
        for (int c = 0; c < 4; c++) q2[c] = __hmul2(qh[c], s2);
    }
    cp_wait<0>();
    __syncthreads();

    // ---- pass 1: scores (HFMA2 chain + fp32 fold) ----
    float sc[32];
    #pragma unroll
    for (int i = 0; i < 32; i++) sc[i] = -1e30f;

    #pragma unroll
    for (int j = 0; j < 125; j++) {
        const int a = j / 25, b = (j / 5) % 5, c5 = j % 5;
        int row = rbase + a * 64 + b * 8 + c5;
        uint4 kk = *(const uint4*)(sK + row * 16 + quarter * 4);
        const half2* kh = (const half2*)&kk;
        half2 p2 = __hmul2(q2[0], kh[0]);
        p2 = __hfma2(q2[1], kh[1], p2);
        p2 = __hfma2(q2[2], kh[2], p2);
        p2 = __hfma2(q2[3], kh[3], p2);
        float2 pf = __half22float2(p2);
        float p = pf.x + pf.y;
        p += __shfl_xor_sync(FULLM, p, 1);
        p += __shfl_xor_sync(FULLM, p, 2);
        if ((j & 3) == quarter) sc[j >> 2] = p;
    }

    // ---- softmax across 4-lane quarter groups ----
    float mx = -1e30f;
    #pragma unroll
    for (int i = 0; i < 32; i++) mx = fmaxf(mx, sc[i]);
    mx = fmaxf(mx, __shfl_xor_sync(FULLM, mx, 1));
    mx = fmaxf(mx, __shfl_xor_sync(FULLM, mx, 2));
    float tot = 0.f;
    #pragma unroll
    for (int i = 0; i < 32; i++) { sc[i] = __expf(sc[i] - mx); tot += sc[i]; }
    tot += __shfl_xor_sync(FULLM, tot, 1);
    tot += __shfl_xor_sync(FULLM, tot, 2);
    float inv = 1.f / tot;

    // ---- pass 2: PV (HFMA2, fp32 spill every 32 iters) ----
    float2 of[4] = {{0.f, 0.f}, {0.f, 0.f}, {0.f, 0.f}, {0.f, 0.f}};
    #pragma unroll
    for (int ch = 0; ch < 4; ch++) {
        half2 oa[4];
        #pragma unroll
        for (int c = 0; c < 4; c++) oa[c] = __float2half2_rn(0.f);
        const int jend = (ch == 3) ? 29 : 32;
        #pragma unroll
        for (int jj = 0; jj < 32; jj++) {
            if (jj >= jend) break;
            const int j = ch * 32 + jj;
            const int a = j / 25, b = (j / 5) % 5, c5 = j % 5;
            float p = __shfl_sync(FULLM, sc[j >> 2], (lane & ~3) | (j & 3));
            half2 p2 = __float2half2_rn(p);
            int row = rbase + a * 64 + b * 8 + c5;
            uint4 vvp = *(const uint4*)(sV + row * 16 + quarter * 4);
            const half2* vh = (const half2*)&vvp;
            oa[0] = __hfma2(p2, vh[0], oa[0]);
            oa[1] = __hfma2(p2, vh[1], oa[1]);
            oa[2] = __hfma2(p2, vh[2], oa[2]);
            oa[3] = __hfma2(p2, vh[3], oa[3]);
        }
        #pragma unroll
        for (int c = 0; c < 4; c++) {
            float2 f = __half22float2(oa[c]);
            of[c].x += f.x;
            of[c].y += f.y;
        }
    }
    size_t ob0 = (size_t)gv * 192 + head * 32 + quarter * 8;
    #pragma unroll
    for (int c = 0; c < 4; c++)
        store_pair(obb, obs, ob0 + 2 * c, of[c].x * inv, of[c].y * inv);
}

// ---------------- orchestration ----------------------------------------------
extern "C" void kernel_launch(void* const* d_in, const int* in_sizes, int n_in,
                              void* d_out, int out_size) {
    const float* x      = (const float*)d_in[0];
    const float* scale1 = (const float*)d_in[1];
    const float* n1_w1  = (const float*)d_in[2];
    const float* n1_b1  = (const float*)d_in[3];
    const float* n1_w2  = (const float*)d_in[4];
    const float* n1_b2  = (const float*)d_in[5];
    const float* qkv_w  = (const float*)d_in[6];
    const float* qkv_b  = (const float*)d_in[7];
    const float* proj_w = (const float*)d_in[8];
    const float* proj_b = (const float*)d_in[9];
    const float* scale2 = (const float*)d_in[10];
    const float* n2_w1  = (const float*)d_in[11];
    const float* n2_b1  = (const float*)d_in[12];
    const float* n2_w2  = (const float*)d_in[13];
    const float* n2_b2  = (const float*)d_in[14];
    const float* mlp_w1 = (const float*)d_in[15];
    const float* mlp_b1 = (const float*)d_in[16];
    const float* mlp_w2 = (const float*)d_in[17];
    const float* mlp_b2 = (const float*)d_in[18];
    float* out = (float*)d_out;

    __half* qkvh;
    __nv_bfloat16 *wb, *wsm, *wb2, *ws2, *w3b, *w3s, *xb, *xs, *obb, *obs, *x2b, *x2s, *mbb, *mbs;
    cudaGetSymbolAddress((void**)&qkvh, g_qkvh);
    cudaGetSymbolAddress((void**)&wb,  g_wb);
    cudaGetSymbolAddress((void**)&wsm, g_wsm);
    cudaGetSymbolAddress((void**)&wb2, g_wb2);
    cudaGetSymbolAddress((void**)&ws2, g_ws2);
    cudaGetSymbolAddress((void**)&w3b, g_w3b);
    cudaGetSymbolAddress((void**)&w3s, g_w3s);
    cudaGetSymbolAddress((void**)&xb,  g_xb);
    cudaGetSymbolAddress((void**)&xs,  g_xs);
    cudaGetSymbolAddress((void**)&obb, g_obb);
    cudaGetSymbolAddress((void**)&obs, g_obs);
    cudaGetSymbolAddress((void**)&x2b, g_x2b);
    cudaGetSymbolAddress((void**)&x2s, g_x2s);
    cudaGetSymbolAddress((void**)&mbb, g_mbb);
    cudaGetSymbolAddress((void**)&mbs, g_mbs);

    cudaFuncSetAttribute(attn_kernel, cudaFuncAttributeMaxDynamicSharedMemorySize, 65536);

    // ---- stage A ----
    colstats_kernel<<<192, 256>>>(x, xb, xs);                        // 1
    gamma1_kernel<<<24, 128>>>(n1_w1, n1_b1);                        // 2
    gamma2_kernel<<<12, 128>>>(n1_w2, n1_b2, scale1);                // 3 (zeroes g_sums)
    convwA_kernel<<<144, 256>>>(qkv_w, proj_w, mlp_w2);              // 4

    // qkv -> fp16 (pos,576), smem-staged coalesced transpose stores // 5
    gemm_kernel<192, 192, false, 0, false, 3, false, false><<<dim3(64, 9), 128>>>(
        wb, wsm, xb, xs, qkv_b, nullptr, (float*)qkvh, nullptr, nullptr, 576, NPOS);

    // attention (fp16 HFMA2) -> ob bf16 pairs (N,C)                 // 6
    attn_kernel<<<dim3(64, 6), 256, 65536>>>(qkvh, obb, obs);

    // proj + residual + stage-B stats -> x2 bf16 pairs only         // 7
    gemm_kernel<192, 192, true, 2, true, 0, true, false><<<dim3(64, 3), 128>>>(
        wb2, ws2, obb, obs, proj_b, x, nullptr, x2b, x2s, 192, NPOS);

    // ---- stage B ----
    gamma1_kernel<<<24, 128>>>(n2_w1, n2_b1);                        // 8
    gamma2_kernel<<<12, 128>>>(n2_w2, n2_b2, scale2);                // 9 (zeroes g_sums)
    convwB_kernel<<<456, 256>>>(mlp_w1, x2b, x2s, mlp_b2, out);      // 10 (w1 split + initout)

    // mlp1 + gelu -> mb bf16 pairs                                  // 11
    gemm_kernel<192, 192, false, 1, false, 0, true, false><<<dim3(64, 12), 128>>>(
        wb, wsm, x2b, x2s, mlp_b1, nullptr, nullptr, mbb, mbs, 768, NPOS);

    // mlp2 split-K x4 atomic-accumulate into pre-initialized out    // 12
    gemm_kernel<192, 768, false, 0, false, 2, false, false><<<dim3(64, 3, 4), 128>>>(
        w3b, w3s, mbb, mbs, mlp_b2, nullptr, out, nullptr, nullptr, 192, NPOS);
}

// round 16
// speedup vs baseline: 1.2026x; 1.0539x over previous
#include <cuda_runtime.h>
#include <cuda_fp16.h>
#include <cuda_bf16.h>
#include <math.h>

#define NPOS 4096
#define FULLM 0xffffffffu

// ---------------- scratch (static device globals; no allocation) -------------
__device__ __half g_qkvh[NPOS * 576];          // (pos, 576) pos-major fp16
__device__ float g_sums[2 * 192];              // per-channel sum / sumsq
__device__ float g_mult[192];                  // scale*gamma/rms
__device__ float g_h[384];                     // norm-MLP hidden
// bf16 big/small pairs
__device__ __nv_bfloat16 g_wb [768 * 192],  g_wsm[768 * 192];    // W bank 0 (qkv, then mlp_w1)
__device__ __nv_bfloat16 g_wb2[192 * 768],  g_ws2[192 * 768];    // W bank 1 (proj)
__device__ __half        g_w3b[192 * 768],  g_w3s[192 * 768];    // W bank 2 (mlp_w2, fp16 pair)
__device__ __nv_bfloat16 g_xb [192 * NPOS], g_xs [192 * NPOS];   // x pairs (C,N)
__device__ __nv_bfloat16 g_obb[NPOS * 192], g_obs[NPOS * 192];   // attn out pairs (N,C)
__device__ __nv_bfloat16 g_x2b[192 * NPOS], g_x2s[192 * NPOS];   // x2 pairs (C,N)
__device__ __half        g_mbh[768 * NPOS];                      // mlp hidden fp16 (C,N)

// ---------------- helpers -----------------------------------------------------
__device__ __forceinline__ unsigned smem_u32(const void* p) {
    return (unsigned)__cvta_generic_to_shared(p);
}
__device__ __forceinline__ void cp16(unsigned dst, const void* src) {
    asm volatile("cp.async.cg.shared.global [%0], [%1], 16;" :: "r"(dst), "l"(src));
}
__device__ __forceinline__ void cp_commit() { asm volatile("cp.async.commit_group;"); }
template <int W> __device__ __forceinline__ void cp_wait() {
    asm volatile("cp.async.wait_group %0;" :: "n"(W));
}
__device__ __forceinline__ void mma_bf16(float* d, const unsigned* a, const unsigned* b) {
    asm volatile(
        "mma.sync.aligned.m16n8k16.row.col.f32.bf16.bf16.f32 "
        "{%0,%1,%2,%3},{%4,%5,%6,%7},{%8,%9},{%0,%1,%2,%3};"
        : "+f"(d[0]), "+f"(d[1]), "+f"(d[2]), "+f"(d[3])
        : "r"(a[0]), "r"(a[1]), "r"(a[2]), "r"(a[3]), "r"(b[0]), "r"(b[1]));
}
__device__ __forceinline__ void mma_f16(float* d, const unsigned* a, const unsigned* b) {
    asm volatile(
        "mma.sync.aligned.m16n8k16.row.col.f32.f16.f16.f32 "
        "{%0,%1,%2,%3},{%4,%5,%6,%7},{%8,%9},{%0,%1,%2,%3};"
        : "+f"(d[0]), "+f"(d[1]), "+f"(d[2]), "+f"(d[3])
        : "r"(a[0]), "r"(a[1]), "r"(a[2]), "r"(a[3]), "r"(b[0]), "r"(b[1]));
}
__device__ __forceinline__ void ldsm_x2_trans(unsigned& r0, unsigned& r1, unsigned addr) {
    asm volatile("ldmatrix.sync.aligned.m8n8.x2.trans.shared.b16 {%0,%1}, [%2];"
                 : "=r"(r0), "=r"(r1) : "r"(addr));
}
__device__ __forceinline__ void store_pair(__nv_bfloat16* pb, __nv_bfloat16* ps,
                                           size_t idx, float v0, float v1) {
    __nv_bfloat16 b0 = __float2bfloat16_rn(v0), b1 = __float2bfloat16_rn(v1);
    __nv_bfloat16 s0 = __float2bfloat16_rn(v0 - __bfloat162float(b0));
    __nv_bfloat16 s1 = __float2bfloat16_rn(v1 - __bfloat162float(b1));
    *(__nv_bfloat162*)(pb + idx) = __halves2bfloat162(b0, b1);
    *(__nv_bfloat162*)(ps + idx) = __halves2bfloat162(s0, s1);
}
__device__ __forceinline__ void split4(float4 v, __nv_bfloat16* db, __nv_bfloat16* ds, int idx) {
    __nv_bfloat16 b0 = __float2bfloat16_rn(v.x), b1 = __float2bfloat16_rn(v.y);
    __nv_bfloat16 b2 = __float2bfloat16_rn(v.z), b3 = __float2bfloat16_rn(v.w);
    *(__nv_bfloat162*)(db + idx)     = __halves2bfloat162(b0, b1);
    *(__nv_bfloat162*)(db + idx + 2) = __halves2bfloat162(b2, b3);
    *(__nv_bfloat162*)(ds + idx) = __halves2bfloat162(
        __float2bfloat16_rn(v.x - __bfloat162float(b0)),
        __float2bfloat16_rn(v.y - __bfloat162float(b1)));
    *(__nv_bfloat162*)(ds + idx + 2) = __halves2bfloat162(
        __float2bfloat16_rn(v.z - __bfloat162float(b2)),
        __float2bfloat16_rn(v.w - __bfloat162float(b3)));
}
__device__ __forceinline__ void split4h(float4 v, __half* db, __half* ds, int idx) {
    __half b0 = __float2half_rn(v.x), b1 = __float2half_rn(v.y);
    __half b2 = __float2half_rn(v.z), b3 = __float2half_rn(v.w);
    *(half2*)(db + idx)     = __halves2half2(b0, b1);
    *(half2*)(db + idx + 2) = __halves2half2(b2, b3);
    *(half2*)(ds + idx) = __halves2half2(
        __float2half_rn(v.x - __half2float(b0)),
        __float2half_rn(v.y - __half2float(b1)));
    *(half2*)(ds + idx + 2) = __halves2half2(
        __float2half_rn(v.z - __half2float(b2)),
        __float2half_rn(v.w - __half2float(b3)));
}

// ---------------- per-channel stats over x + bf16 pair conversion -------------
__global__ void colstats_kernel(const float* __restrict__ x,
                                __nv_bfloat16* __restrict__ xb,
                                __nv_bfloat16* __restrict__ xs) {
    int c = blockIdx.x;
    const float* p = x + c * NPOS;
    float s = 0.f, s2 = 0.f;
    for (int i = threadIdx.x; i < NPOS; i += 256) {
        float v = p[i];
        s += v;
        s2 = fmaf(v, v, s2);
        __nv_bfloat16 b = __float2bfloat16_rn(v);
        xb[c * NPOS + i] = b;
        xs[c * NPOS + i] = __float2bfloat16_rn(v - __bfloat162float(b));
    }
    __shared__ float sh0[256], sh1[256];
    sh0[threadIdx.x] = s; sh1[threadIdx.x] = s2;
    __syncthreads();
    for (int o = 128; o > 0; o >>= 1) {
        if (threadIdx.x < o) {
            sh0[threadIdx.x] += sh0[threadIdx.x + o];
            sh1[threadIdx.x] += sh1[threadIdx.x + o];
        }
        __syncthreads();
    }
    if (threadIdx.x == 0) {
        g_sums[c]       = sh0[0];
        g_sums[192 + c] = sh1[0];
    }
}

// ---------------- norm-MLP layer 1 --------------------------------------------
__global__ void gamma1_kernel(const float* __restrict__ w1, const float* __restrict__ b1) {
    const int warp = threadIdx.x >> 5, lane = threadIdx.x & 31;
    const int ob = blockIdx.x * 16 + warp * 4;
    float a0 = 0.f, a1 = 0.f, a2 = 0.f, a3 = 0.f;
    #pragma unroll
    for (int j = 0; j < 6; j++) {
        float sv = g_sums[lane + j * 32] * (1.0f / 4096.0f);
        a0 = fmaf(sv, w1[(ob + 0) * 192 + lane + j * 32], a0);
        a1 = fmaf(sv, w1[(ob + 1) * 192 + lane + j * 32], a1);
        a2 = fmaf(sv, w1[(ob + 2) * 192 + lane + j * 32], a2);
        a3 = fmaf(sv, w1[(ob + 3) * 192 + lane + j * 32], a3);
    }
    #pragma unroll
    for (int off = 16; off; off >>= 1) {
        a0 += __shfl_xor_sync(FULLM, a0, off);
        a1 += __shfl_xor_sync(FULLM, a1, off);
        a2 += __shfl_xor_sync(FULLM, a2, off);
        a3 += __shfl_xor_sync(FULLM, a3, off);
    }
    if (lane == 0) {
        g_h[ob + 0] = fmaxf(a0 + b1[ob + 0], 0.f);
        g_h[ob + 1] = fmaxf(a1 + b1[ob + 1], 0.f);
        g_h[ob + 2] = fmaxf(a2 + b1[ob + 2], 0.f);
        g_h[ob + 3] = fmaxf(a3 + b1[ob + 3], 0.f);
    }
}

// ---------------- norm-MLP layer 2 -> g_mult; zeroes g_sums -------------------
__global__ void gamma2_kernel(const float* __restrict__ w2, const float* __restrict__ b2,
                              const float* __restrict__ scale) {
    const int warp = threadIdx.x >> 5, lane = threadIdx.x & 31;
    const int ob = blockIdx.x * 16 + warp * 4;
    float a0 = 0.f, a1 = 0.f, a2 = 0.f, a3 = 0.f;
    #pragma unroll
    for (int j = 0; j < 12; j++) {
        float hv = g_h[lane + j * 32];
        a0 = fmaf(hv, w2[(ob + 0) * 384 + lane + j * 32], a0);
        a1 = fmaf(hv, w2[(ob + 1) * 384 + lane + j * 32], a1);
        a2 = fmaf(hv, w2[(ob + 2) * 384 + lane + j * 32], a2);
        a3 = fmaf(hv, w2[(ob + 3) * 384 + lane + j * 32], a3);
    }
    #pragma unroll
    for (int off = 16; off; off >>= 1) {
        a0 += __shfl_xor_sync(FULLM, a0, off);
        a1 += __shfl_xor_sync(FULLM, a1, off);
        a2 += __shfl_xor_sync(FULLM, a2, off);
        a3 += __shfl_xor_sync(FULLM, a3, off);
    }
    if (lane == 0) {
        #pragma unroll
        for (int u = 0; u < 4; u++) {
            float a = (u == 0 ? a0 : u == 1 ? a1 : u == 2 ? a2 : a3) + b2[ob + u];
            float gamma = 1.f / (1.f + expf(-a));
            float rms = sqrtf(g_sums[192 + ob + u] * (1.0f / 4096.0f) + 1e-6f);
            g_mult[ob + u] = scale[ob + u] * gamma / rms;
            g_sums[ob + u] = 0.f;
            g_sums[192 + ob + u] = 0.f;
        }
    }
}

// ---------------- convwA: qkv_w (x g_mult) + proj_w (bf16) + mlp_w2 (fp16) ----
__global__ void convwA_kernel(const float* __restrict__ qkvw, const float* __restrict__ projw,
                              const float* __restrict__ w2m) {
    int base = blockIdx.x * 256 + threadIdx.x;       // 0..36863
    #pragma unroll
    for (int s = 0; s < 2; s++) {
        int i4 = base + s * 36864;
        if (i4 < 27648) {                    // qkv_w: fold g_mult
            int idx = i4 * 4;
            float4 t = ((const float4*)qkvw)[i4];
            int m = idx % 192;
            t.x *= g_mult[m]; t.y *= g_mult[m + 1]; t.z *= g_mult[m + 2]; t.w *= g_mult[m + 3];
            split4(t, g_wb, g_wsm, idx);
        } else if (i4 < 36864) {             // proj_w
            int j = i4 - 27648;
            split4(((const float4*)projw)[j], g_wb2, g_ws2, j * 4);
        } else {                             // mlp_w2 -> fp16 pair
            int j = i4 - 36864;
            split4h(((const float4*)w2m)[j], g_w3b, g_w3s, j * 4);
        }
    }
}

// ---------------- convwB: mlp_w1 (x g_mult) split + initout -------------------
__global__ void convwB_kernel(const float* __restrict__ w1,
                              const __nv_bfloat16* __restrict__ x2b,
                              const __nv_bfloat16* __restrict__ x2s,
                              const float* __restrict__ bias, float* __restrict__ out) {
    int base = blockIdx.x * 256 + threadIdx.x;       // 0..116735
    #pragma unroll
    for (int s = 0; s < 2; s++) {
        int i4 = base + s * 116736;
        if (i4 < 36864) {                    // mlp_w1: fold g_mult
            int idx = i4 * 4;
            float4 v = ((const float4*)w1)[i4];
            int m = idx % 192;
            v.x *= g_mult[m]; v.y *= g_mult[m + 1]; v.z *= g_mult[m + 2]; v.w *= g_mult[m + 3];
            split4(v, g_wb, g_wsm, idx);
        } else if (i4 < 233472) {            // initout (196608 float4s)
            int j = i4 - 36864;
            float b = bias[j >> 10];
            uint2 pb = *(const uint2*)(x2b + j * 4);
            uint2 psm = *(const uint2*)(x2s + j * 4);
            float2 b0 = __bfloat1622float2(*(__nv_bfloat162*)&pb.x);
            float2 b1 = __bfloat1622float2(*(__nv_bfloat162*)&pb.y);
            float2 s0 = __bfloat1622float2(*(__nv_bfloat162*)&psm.x);
            float2 s1 = __bfloat1622float2(*(__nv_bfloat162*)&psm.y);
            float4 v = make_float4(b0.x + s0.x + b, b0.y + s0.y + b,
                                   b1.x + s1.x + b, b1.y + s1.y + b);
            ((float4*)out)[j] = v;
        }
    }
}

// ---------------- GEMM v10: bf16x3 pairs OR fp16 2-term, cp.async 3-stage -----
// OUTM: 0 none/pairs, 2 atomicAdd (Co,N), 3 fp16 (N,Co) staged, 4 fp16 (Co,N).
// F16: A fp16 pair + B fp16 single (2 MMAs); only valid with BNMAJ=false.
template <int CI, int CIFULL, bool BNMAJ, int EPI, bool STATS, int OUTM, bool PAIRS, bool F16>
__global__ void __launch_bounds__(128)
gemm_kernel(const __nv_bfloat16* __restrict__ Awb, const __nv_bfloat16* __restrict__ Aws,
            const __nv_bfloat16* __restrict__ Bxb, const __nv_bfloat16* __restrict__ Bxs,
            const float* __restrict__ bias, const float* __restrict__ res,
            float* __restrict__ out, __nv_bfloat16* __restrict__ pb,
            __nv_bfloat16* __restrict__ ps, int Co, int N) {
    constexpr int NK = CI / 16;
    constexpr int BW = BNMAJ ? (64 * 12) : (16 * 36);
    constexpr int NBUF = F16 ? 1 : 2;
    __shared__ uint sA[3][2][64 * 12];
    __shared__ uint sB[3][NBUF][BW];
    __shared__ __half sT[(OUTM == 3) ? 64 * 72 : 8];

    const int bn = blockIdx.x * 64;
    const int bm = blockIdx.y * 64;
    const int kbase = blockIdx.z * CI;
    const int tid = threadIdx.x;
    const int warp = tid >> 5, lane = tid & 31;
    const int gid = lane >> 2, tig = lane & 3;
    const int wmb = (warp >> 1) * 32;
    const int wnb = (warp & 1) * 32;

    auto stage = [&](int t, int st) {
        const int kk = kbase + t * 16;
        {
            int row = tid >> 1, ch = tid & 1;
            size_t go = (size_t)(bm + row) * CIFULL + kk + ch * 8;
            cp16(smem_u32(&sA[st][0][row * 12 + ch * 4]), Awb + go);
            cp16(smem_u32(&sA[st][1][row * 12 + ch * 4]), Aws + go);
        }
        if (BNMAJ) {
            int row = tid >> 1, ch = tid & 1;
            size_t go = (size_t)(bn + row) * CIFULL + kk + ch * 8;
            cp16(smem_u32(&sB[st][0][row * 12 + ch * 4]), Bxb + go);
            cp16(smem_u32(&sB[st][NBUF - 1][row * 12 + ch * 4]), Bxs + go);
        } else {
            int row = tid >> 3, ch = tid & 7;
            size_t go = (size_t)(kk + row) * N + bn + ch * 8;
            cp16(smem_u32((char*)&sB[st][0][0] + row * 144 + ch * 16), Bxb + go);
            if (!F16)
                cp16(smem_u32((char*)&sB[st][NBUF - 1][0] + row * 144 + ch * 16), Bxs + go);
        }
        cp_commit();
    };

    float d[2][4][4];
    #pragma unroll
    for (int mt = 0; mt < 2; mt++)
        #pragma unroll
        for (int j = 0; j < 4; j++)
            #pragma unroll
            for (int e = 0; e < 4; e++) d[mt][j][e] = 0.f;

    stage(0, 0);
    stage(1, 1);

    #pragma unroll 1
    for (int t = 0; t < NK; t++) {
        const int st = t % 3;
        if (t == NK - 1) cp_wait<0>(); else cp_wait<1>();
        __syncthreads();

        unsigned Ab[2][4], As[2][4];
        #pragma unroll
        for (int mt = 0; mt < 2; mt++) {
            int m0 = wmb + 16 * mt + gid;
            Ab[mt][0] = sA[st][0][m0 * 12 + tig];
            Ab[mt][1] = sA[st][0][(m0 + 8) * 12 + tig];
            Ab[mt][2] = sA[st][0][m0 * 12 + tig + 4];
            Ab[mt][3] = sA[st][0][(m0 + 8) * 12 + tig + 4];
            As[mt][0] = sA[st][1][m0 * 12 + tig];
            As[mt][1] = sA[st][1][(m0 + 8) * 12 + tig];
            As[mt][2] = sA[st][1][m0 * 12 + tig + 4];
            As[mt][3] = sA[st][1][(m0 + 8) * 12 + tig + 4];
        }
        #pragma unroll
        for (int j = 0; j < 4; j++) {
            unsigned Bb[2], Bs[2];
            if (BNMAJ) {
                int n0 = wnb + 8 * j + gid;
                Bb[0] = sB[st][0][n0 * 12 + tig];
                Bb[1] = sB[st][0][n0 * 12 + tig + 4];
                Bs[0] = sB[st][NBUF - 1][n0 * 12 + tig];
                Bs[1] = sB[st][NBUF - 1][n0 * 12 + tig + 4];
            } else {
                int boff = ((lane & 15) * 72 + wnb + 8 * j) * 2;
                ldsm_x2_trans(Bb[0], Bb[1], smem_u32((char*)&sB[st][0][0] + boff));
                if (!F16)
                    ldsm_x2_trans(Bs[0], Bs[1], smem_u32((char*)&sB[st][NBUF - 1][0] + boff));
            }
            #pragma unroll
            for (int mt = 0; mt < 2; mt++) {
                if (F16) {
                    mma_f16(d[mt][j], Ab[mt], Bb);
                    mma_f16(d[mt][j], As[mt], Bb);
                } else {
                    mma_bf16(d[mt][j], Ab[mt], Bb);
                    mma_bf16(d[mt][j], As[mt], Bb);
                    mma_bf16(d[mt][j], Ab[mt], Bs);
                }
            }
        }
        if (t + 2 < NK) stage(t + 2, (t + 2) % 3);
    }

    // ---- epilogue ----
    const int gn0 = bn + wnb + 2 * tig;
    #pragma unroll
    for (int mt = 0; mt < 2; mt++) {
        #pragma unroll
        for (int half = 0; half < 2; half++) {
            int m = bm + wmb + 16 * mt + gid + 8 * half;
            float bv = (OUTM == 2) ? 0.f : bias[m];
            float v[8];
            #pragma unroll
            for (int j = 0; j < 4; j++) {
                v[2 * j]     = d[mt][j][2 * half]     + bv;
                v[2 * j + 1] = d[mt][j][2 * half + 1] + bv;
            }
            if (EPI == 1) {
                #pragma unroll
                for (int e = 0; e < 8; e++) {
                    float u = v[e];
                    v[e] = u * 0.5f * (1.f + erff(u * 0.70710678118654752f));
                }
            }
            if (EPI == 2) {
                #pragma unroll
                for (int j = 0; j < 4; j++) {
                    float2 r2 = *(const float2*)&res[(size_t)m * N + gn0 + 8 * j];
                    v[2 * j] += r2.x; v[2 * j + 1] += r2.y;
                }
            }
            if (STATS) {
                float ls = 0.f, ls2 = 0.f;
                #pragma unroll
                for (int e = 0; e < 8; e++) { ls += v[e]; ls2 = fmaf(v[e], v[e], ls2); }
                ls  += __shfl_xor_sync(FULLM, ls, 1);  ls  += __shfl_xor_sync(FULLM, ls, 2);
                ls2 += __shfl_xor_sync(FULLM, ls2, 1); ls2 += __shfl_xor_sync(FULLM, ls2, 2);
                if (tig == 0) {
                    atomicAdd(&g_sums[m], ls);
                    atomicAdd(&g_sums[192 + m], ls2);
                }
            }
            if (PAIRS) {
                #pragma unroll
                for (int j = 0; j < 4; j++)
                    store_pair(pb, ps, (size_t)m * N + gn0 + 8 * j, v[2 * j], v[2 * j + 1]);
            }
            if (OUTM == 3) {
                int ml = wmb + 16 * mt + gid + 8 * half;
                #pragma unroll
                for (int j = 0; j < 4; j++) {
                    int nl = wnb + 2 * tig + 8 * j;
                    sT[nl * 72 + ml]       = __float2half(v[2 * j]);
                    sT[(nl + 1) * 72 + ml] = __float2half(v[2 * j + 1]);
                }
            } else if (OUTM == 2) {
                #pragma unroll
                for (int j = 0; j < 4; j++) {
                    atomicAdd(&out[(size_t)m * N + gn0 + 8 * j],     v[2 * j]);
                    atomicAdd(&out[(size_t)m * N + gn0 + 8 * j + 1], v[2 * j + 1]);
                }
            } else if (OUTM == 4) {
                __half* oh2 = (__half*)out;
                #pragma unroll
                for (int j = 0; j < 4; j++)
                    *(half2*)(oh2 + (size_t)m * N + gn0 + 8 * j) =
                        __floats2half2_rn(v[2 * j], v[2 * j + 1]);
            }
        }
    }
    if (OUTM == 3) {
        __syncthreads();
        __half* oh = (__half*)out;
        #pragma unroll
        for (int i = 0; i < 4; i++) {
            int idx = tid + i * 128;
            int row = idx >> 3, ch = idx & 7;
            *(uint4*)(oh + (size_t)(bn + row) * Co + bm + ch * 8) =
                *(const uint4*)(sT + row * 72 + ch * 8);
        }
    }
}

// ---------------- 3D neighborhood attention (fp16, HFMA2 math) ----------------
__global__ void __launch_bounds__(256) attn_kernel(const __half* __restrict__ qkvh,
                                                   __nv_bfloat16* __restrict__ obb,
                                                   __nv_bfloat16* __restrict__ obs) {
    extern __shared__ __align__(16) half2 sKV[];   // sK[8192] then sV[8192]
    half2* sK = sKV;
    half2* sV = sKV + 8192;

    const int tile = blockIdx.x, head = blockIdx.y;
    const int tid = threadIdx.x;

    const int Td = ((tile >> 4) & 3) * 4, Th = ((tile >> 2) & 3) * 4, Tw = (tile & 3) * 4;
    const int Bd = min(max(Td - 2, 0), 8);
    const int Bh = min(max(Th - 2, 0), 8);
    const int Bw = min(max(Tw - 2, 0), 8);

    #pragma unroll
    for (int it = 0; it < 16; it++) {
        int i = tid + it * 256;
        int row = i >> 3, g = i & 7;
        int rd = row >> 6, rh = (row >> 3) & 7, rw = row & 7;
        int gpos = ((Bd + rd) << 8) + ((Bh + rh) << 4) + (Bw + rw);
        int mat = g >> 2, c = g & 3;
        const __half* src = qkvh + (size_t)gpos * 576 + 192 + 192 * mat + head * 32 + c * 8;
        half2* dst = (mat ? sV : sK) + row * 16 + c * 4;
        cp16(smem_u32(dst), src);
    }
    cp_commit();

    const int quarter = tid & 3, vox = tid >> 2;
    const int aw = vox & 3, ah = (vox >> 2) & 3, ad = vox >> 4;
    const int vd = Td + ad, vh = Th + ah, vw = Tw + aw;
    const int gv = (vd << 8) + (vh << 4) + vw;
    const int ld = min(max(vd - 2, 0), 11) - Bd;
    const int lh = min(max(vh - 2, 0), 11) - Bh;
    const int lw = min(max(vw - 2, 0), 11) - Bw;
    const int rbase = ld * 64 + lh * 8 + lw;
    const int lane = tid & 31;

    half2 q2[4];
    {
        const __half* qp = qkvh + (size_t)gv * 576 + head * 32 + quarter * 8;
        uint4 qq = *(const uint4*)qp;
        const half2* qh = (const half2*)&qq;
        half2 s2 = __float2half2_rn(0.17677669529663687f);
        #pragma unroll
        for (int c = 0; c < 4; c++) q2[c] = __hmul2(qh[c], s2);
    }
    cp_wait<0>();
    __syncthreads();

    float sc[32];
    #pragma unroll
    for (int i = 0; i < 32; i++) sc[i] = -1e30f;

    #pragma unroll
    for (int j = 0; j < 125; j++) {
        const int a = j / 25, b = (j / 5) % 5, c5 = j % 5;
        int row = rbase + a * 64 + b * 8 + c5;
        uint4 kk = *(const uint4*)(sK + row * 16 + quarter * 4);
        const half2* kh = (const half2*)&kk;
        half2 p2 = __hmul2(q2[0], kh[0]);
        p2 = __hfma2(q2[1], kh[1], p2);
        p2 = __hfma2(q2[2], kh[2], p2);
        p2 = __hfma2(q2[3], kh[3], p2);
        float2 pf = __half22float2(p2);
        float p = pf.x + pf.y;
        p += __shfl_xor_sync(FULLM, p, 1);
        p += __shfl_xor_sync(FULLM, p, 2);
        if ((j & 3) == quarter) sc[j >> 2] = p;
    }

    float mx = -1e30f;
    #pragma unroll
    for (int i = 0; i < 32; i++) mx = fmaxf(mx, sc[i]);
    mx = fmaxf(mx, __shfl_xor_sync(FULLM, mx, 1));
    mx = fmaxf(mx, __shfl_xor_sync(FULLM, mx, 2));
    float tot = 0.f;
    #pragma unroll
    for (int i = 0; i < 32; i++) { sc[i] = __expf(sc[i] - mx); tot += sc[i]; }
    tot += __shfl_xor_sync(FULLM, tot, 1);
    tot += __shfl_xor_sync(FULLM, tot, 2);
    float inv = 1.f / tot;

    float2 of[4] = {{0.f, 0.f}, {0.f, 0.f}, {0.f, 0.f}, {0.f, 0.f}};
    #pragma unroll
    for (int ch = 0; ch < 4; ch++) {
        half2 oa[4];
        #pragma unroll
        for (int c = 0; c < 4; c++) oa[c] = __float2half2_rn(0.f);
        const int jend = (ch == 3) ? 29 : 32;
        #pragma unroll
        for (int jj = 0; jj < 32; jj++) {
            if (jj >= jend) break;
            const int j = ch * 32 + jj;
            const int a = j / 25, b = (j / 5) % 5, c5 = j % 5;
            float p = __shfl_sync(FULLM, sc[j >> 2], (lane & ~3) | (j & 3));
            half2 p2 = __float2half2_rn(p);
            int row = rbase + a * 64 + b * 8 + c5;
            uint4 vvp = *(const uint4*)(sV + row * 16 + quarter * 4);
            const half2* vh = (const half2*)&vvp;
            oa[0] = __hfma2(p2, vh[0], oa[0]);
            oa[1] = __hfma2(p2, vh[1], oa[1]);
            oa[2] = __hfma2(p2, vh[2], oa[2]);
            oa[3] = __hfma2(p2, vh[3], oa[3]);
        }
        #pragma unroll
        for (int c = 0; c < 4; c++) {
            float2 f = __half22float2(oa[c]);
            of[c].x += f.x;
            of[c].y += f.y;
        }
    }
    size_t ob0 = (size_t)gv * 192 + head * 32 + quarter * 8;
    #pragma unroll
    for (int c = 0; c < 4; c++)
        store_pair(obb, obs, ob0 + 2 * c, of[c].x * inv, of[c].y * inv);
}

// ---------------- orchestration ----------------------------------------------
extern "C" void kernel_launch(void* const* d_in, const int* in_sizes, int n_in,
                              void* d_out, int out_size) {
    const float* x      = (const float*)d_in[0];
    const float* scale1 = (const float*)d_in[1];
    const float* n1_w1  = (const float*)d_in[2];
    const float* n1_b1  = (const float*)d_in[3];
    const float* n1_w2  = (const float*)d_in[4];
    const float* n1_b2  = (const float*)d_in[5];
    const float* qkv_w  = (const float*)d_in[6];
    const float* qkv_b  = (const float*)d_in[7];
    const float* proj_w = (const float*)d_in[8];
    const float* proj_b = (const float*)d_in[9];
    const float* scale2 = (const float*)d_in[10];
    const float* n2_w1  = (const float*)d_in[11];
    const float* n2_b1  = (const float*)d_in[12];
    const float* n2_w2  = (const float*)d_in[13];
    const float* n2_b2  = (const float*)d_in[14];
    const float* mlp_w1 = (const float*)d_in[15];
    const float* mlp_b1 = (const float*)d_in[16];
    const float* mlp_w2 = (const float*)d_in[17];
    const float* mlp_b2 = (const float*)d_in[18];
    float* out = (float*)d_out;

    __half *qkvh, *w3b, *w3s, *mbh;
    __nv_bfloat16 *wb, *wsm, *wb2, *ws2, *xb, *xs, *obb, *obs, *x2b, *x2s;
    cudaGetSymbolAddress((void**)&qkvh, g_qkvh);
    cudaGetSymbolAddress((void**)&wb,  g_wb);
    cudaGetSymbolAddress((void**)&wsm, g_wsm);
    cudaGetSymbolAddress((void**)&wb2, g_wb2);
    cudaGetSymbolAddress((void**)&ws2, g_ws2);
    cudaGetSymbolAddress((void**)&w3b, g_w3b);
    cudaGetSymbolAddress((void**)&w3s, g_w3s);
    cudaGetSymbolAddress((void**)&xb,  g_xb);
    cudaGetSymbolAddress((void**)&xs,  g_xs);
    cudaGetSymbolAddress((void**)&obb, g_obb);
    cudaGetSymbolAddress((void**)&obs, g_obs);
    cudaGetSymbolAddress((void**)&x2b, g_x2b);
    cudaGetSymbolAddress((void**)&x2s, g_x2s);
    cudaGetSymbolAddress((void**)&mbh, g_mbh);

    cudaFuncSetAttribute(attn_kernel, cudaFuncAttributeMaxDynamicSharedMemorySize, 65536);

    // ---- stage A ----
    colstats_kernel<<<192, 256>>>(x, xb, xs);                        // 1
    gamma1_kernel<<<24, 128>>>(n1_w1, n1_b1);                        // 2
    gamma2_kernel<<<12, 128>>>(n1_w2, n1_b2, scale1);                // 3 (zeroes g_sums)
    convwA_kernel<<<144, 256>>>(qkv_w, proj_w, mlp_w2);              // 4

    // qkv -> fp16 (pos,576), smem-staged coalesced transpose stores // 5
    gemm_kernel<192, 192, false, 0, false, 3, false, false><<<dim3(64, 9), 128>>>(
        wb, wsm, xb, xs, qkv_b, nullptr, (float*)qkvh, nullptr, nullptr, 576, NPOS);

    // attention (fp16 HFMA2) -> ob bf16 pairs (N,C)                 // 6
    attn_kernel<<<dim3(64, 6), 256, 65536>>>(qkvh, obb, obs);

    // proj + residual + stage-B stats -> x2 bf16 pairs only         // 7
    gemm_kernel<192, 192, true, 2, true, 0, true, false><<<dim3(64, 3), 128>>>(
        wb2, ws2, obb, obs, proj_b, x, nullptr, x2b, x2s, 192, NPOS);

    // ---- stage B ----
    gamma1_kernel<<<24, 128>>>(n2_w1, n2_b1);                        // 8
    gamma2_kernel<<<12, 128>>>(n2_w2, n2_b2, scale2);                // 9 (zeroes g_sums)
    convwB_kernel<<<456, 256>>>(mlp_w1, x2b, x2s, mlp_b2, out);      // 10 (w1 split + initout)

    // mlp1 + gelu -> mb fp16 single (Co,N)                          // 11
    gemm_kernel<192, 192, false, 1, false, 4, false, false><<<dim3(64, 12), 128>>>(
        wb, wsm, x2b, x2s, mlp_b1, nullptr, (float*)mbh, nullptr, nullptr, 768, NPOS);

    // mlp2 split-K x4 (fp16 2-term) atomic-accumulate into out      // 12
    gemm_kernel<192, 768, false, 0, false, 2, false, true><<<dim3(64, 3, 4), 128>>>(
        (const __nv_bfloat16*)w3b, (const __nv_bfloat16*)w3s,
        (const __nv_bfloat16*)mbh, nullptr, mlp_b2, nullptr, out, nullptr, nullptr, 192, NPOS);
}